// round 1
// baseline (speedup 1.0000x reference)
#include <cuda_runtime.h>
#include <math.h>

#define D_   1024
#define BQ_  1024
#define NC_  16384
#define H_   8
#define HD_  128

// ---------------- scratch (device globals: allocation-free) ----------------
__device__ float g_buf [NC_ * D_];                 // key proj hidden (in-place LN+GELU)
__device__ float g_KP  [NC_ * D_];
__device__ float g_KH  [NC_ * D_];
__device__ float g_qbuf[BQ_ * D_];
__device__ float g_QP  [BQ_ * D_];
__device__ float g_QH  [BQ_ * D_];
__device__ float g_GQK [(size_t)BQ_ * NC_];        // qp @ kp^T
__device__ float g_S   [(size_t)H_ * BQ_ * NC_];   // per-head scaled scores [H][B][N]
__device__ float g_ksq [NC_], g_krn[NC_];
__device__ float g_qsq [BQ_], g_qrn[BQ_];
__device__ float g_m   [BQ_ * H_], g_l[BQ_ * H_];

// ---------------- 128x128x16 SGEMM, NN, +bias: C[M,Nc] = A[M,K]@B[K,Nc]+bias ----
__global__ __launch_bounds__(256) void sgemm_nn_bias(
    const float* __restrict__ A, const float* __restrict__ B,
    const float* __restrict__ bias, float* __restrict__ C,
    int M, int Ncols, int K)
{
    __shared__ float As[16][128];
    __shared__ float Bs[16][128];
    int tid = threadIdx.x;
    int bm = blockIdx.y * 128;
    int bn = blockIdx.x * 128;
    int tx = tid & 15, ty = tid >> 4;
    int m0 = ty * 8, n0 = tx * 8;

    float acc[8][8];
    #pragma unroll
    for (int i = 0; i < 8; i++)
        #pragma unroll
        for (int j = 0; j < 8; j++) acc[i][j] = 0.f;

    for (int k0 = 0; k0 < K; k0 += 16) {
        #pragma unroll
        for (int i = 0; i < 2; i++) {
            int f   = tid + i * 256;          // float4 index 0..511
            int row = f >> 2;                 // 0..127
            int kc  = (f & 3) << 2;           // 0,4,8,12
            float4 va = *reinterpret_cast<const float4*>(
                &A[(size_t)(bm + row) * K + k0 + kc]);
            As[kc+0][row] = va.x; As[kc+1][row] = va.y;
            As[kc+2][row] = va.z; As[kc+3][row] = va.w;
            int kr = f >> 5;                  // 0..15
            int nc = (f & 31) << 2;           // 0..124
            *reinterpret_cast<float4*>(&Bs[kr][nc]) =
                *reinterpret_cast<const float4*>(&B[(size_t)(k0 + kr) * Ncols + bn + nc]);
        }
        __syncthreads();
        #pragma unroll
        for (int k = 0; k < 16; k++) {
            float ra[8], rb[8];
            *(float4*)&ra[0] = *(float4*)&As[k][m0];
            *(float4*)&ra[4] = *(float4*)&As[k][m0 + 4];
            *(float4*)&rb[0] = *(float4*)&Bs[k][n0];
            *(float4*)&rb[4] = *(float4*)&Bs[k][n0 + 4];
            #pragma unroll
            for (int i = 0; i < 8; i++)
                #pragma unroll
                for (int j = 0; j < 8; j++) acc[i][j] += ra[i] * rb[j];
        }
        __syncthreads();
    }
    #pragma unroll
    for (int i = 0; i < 8; i++) {
        int gm = bm + m0 + i;
        #pragma unroll
        for (int j0 = 0; j0 < 8; j0 += 4) {
            float4 v;
            v.x = acc[i][j0+0] + bias[bn + n0 + j0 + 0];
            v.y = acc[i][j0+1] + bias[bn + n0 + j0 + 1];
            v.z = acc[i][j0+2] + bias[bn + n0 + j0 + 2];
            v.w = acc[i][j0+3] + bias[bn + n0 + j0 + 3];
            *reinterpret_cast<float4*>(&C[(size_t)gm * Ncols + bn + n0 + j0]) = v;
        }
    }
}

// ---------------- 128x128x16 SGEMM, NT: C = scale * A[M,K]@B[Nc,K]^T ------------
// z-dim: per-head mode. koff = z*kOffStride selects K slice; C += z*zStrideC.
__global__ __launch_bounds__(256) void sgemm_nt(
    const float* __restrict__ A, const float* __restrict__ B, float* __restrict__ C,
    int M, int Ncols, int K, int lda, int ldb,
    int kOffStride, size_t zStrideC, float scale)
{
    __shared__ float As[16][128];
    __shared__ float Bs[16][128];
    int tid = threadIdx.x;
    int bm = blockIdx.y * 128;
    int bn = blockIdx.x * 128;
    int z  = blockIdx.z;
    int koff = z * kOffStride;
    int tx = tid & 15, ty = tid >> 4;
    int m0 = ty * 8, n0 = tx * 8;

    float acc[8][8];
    #pragma unroll
    for (int i = 0; i < 8; i++)
        #pragma unroll
        for (int j = 0; j < 8; j++) acc[i][j] = 0.f;

    for (int k0 = 0; k0 < K; k0 += 16) {
        #pragma unroll
        for (int i = 0; i < 2; i++) {
            int f   = tid + i * 256;
            int row = f >> 2;
            int kc  = (f & 3) << 2;
            float4 va = *reinterpret_cast<const float4*>(
                &A[(size_t)(bm + row) * lda + koff + k0 + kc]);
            As[kc+0][row] = va.x; As[kc+1][row] = va.y;
            As[kc+2][row] = va.z; As[kc+3][row] = va.w;
            float4 vb = *reinterpret_cast<const float4*>(
                &B[(size_t)(bn + row) * ldb + koff + k0 + kc]);
            Bs[kc+0][row] = vb.x; Bs[kc+1][row] = vb.y;
            Bs[kc+2][row] = vb.z; Bs[kc+3][row] = vb.w;
        }
        __syncthreads();
        #pragma unroll
        for (int k = 0; k < 16; k++) {
            float ra[8], rb[8];
            *(float4*)&ra[0] = *(float4*)&As[k][m0];
            *(float4*)&ra[4] = *(float4*)&As[k][m0 + 4];
            *(float4*)&rb[0] = *(float4*)&Bs[k][n0];
            *(float4*)&rb[4] = *(float4*)&Bs[k][n0 + 4];
            #pragma unroll
            for (int i = 0; i < 8; i++)
                #pragma unroll
                for (int j = 0; j < 8; j++) acc[i][j] += ra[i] * rb[j];
        }
        __syncthreads();
    }
    float* Cz = C + (size_t)z * zStrideC;
    #pragma unroll
    for (int i = 0; i < 8; i++) {
        int gm = bm + m0 + i;
        #pragma unroll
        for (int j0 = 0; j0 < 8; j0 += 4) {
            float4 v;
            v.x = acc[i][j0+0] * scale;
            v.y = acc[i][j0+1] * scale;
            v.z = acc[i][j0+2] * scale;
            v.w = acc[i][j0+3] * scale;
            *reinterpret_cast<float4*>(&Cz[(size_t)gm * Ncols + bn + n0 + j0]) = v;
        }
    }
}

// ---------------- LayerNorm + exact GELU, in place, row length D_ ----------------
__global__ __launch_bounds__(256) void ln_gelu_kernel(
    float* __restrict__ X, const float* __restrict__ g, const float* __restrict__ be)
{
    __shared__ float sh[256];
    int row = blockIdx.x;
    float* xr = X + (size_t)row * D_;
    float v[4]; float s = 0.f, s2 = 0.f;
    #pragma unroll
    for (int i = 0; i < 4; i++) {
        int c = threadIdx.x + i * 256;
        v[i] = xr[c]; s += v[i]; s2 += v[i] * v[i];
    }
    sh[threadIdx.x] = s; __syncthreads();
    for (int st = 128; st > 0; st >>= 1) {
        if (threadIdx.x < st) sh[threadIdx.x] += sh[threadIdx.x + st];
        __syncthreads();
    }
    float mean = sh[0] * (1.f / D_); __syncthreads();
    sh[threadIdx.x] = s2; __syncthreads();
    for (int st = 128; st > 0; st >>= 1) {
        if (threadIdx.x < st) sh[threadIdx.x] += sh[threadIdx.x + st];
        __syncthreads();
    }
    float var  = sh[0] * (1.f / D_) - mean * mean;
    float rstd = rsqrtf(var + 1e-5f);
    #pragma unroll
    for (int i = 0; i < 4; i++) {
        int c = threadIdx.x + i * 256;
        float y = (v[i] - mean) * rstd * g[c] + be[c];
        xr[c] = 0.5f * y * (1.f + erff(y * 0.7071067811865475f));
    }
}

// ---------------- per-row sum of squares + reciprocal norm ----------------
__global__ __launch_bounds__(256) void row_stats_kernel(
    const float* __restrict__ X, float* __restrict__ sq, float* __restrict__ rn)
{
    __shared__ float sh[256];
    int row = blockIdx.x;
    const float* xr = X + (size_t)row * D_;
    float s2 = 0.f;
    #pragma unroll
    for (int i = 0; i < 4; i++) { float v = xr[threadIdx.x + i * 256]; s2 += v * v; }
    sh[threadIdx.x] = s2; __syncthreads();
    for (int st = 128; st > 0; st >>= 1) {
        if (threadIdx.x < st) sh[threadIdx.x] += sh[threadIdx.x + st];
        __syncthreads();
    }
    if (threadIdx.x == 0) { sq[row] = sh[0]; rn[row] = rsqrtf(sh[0]); }
}

// ---------------- online softmax stats per (b,h): max m, l = sum exp(s-m) -------
__global__ __launch_bounds__(256) void softmax_stats_kernel(
    const float* __restrict__ S, float* __restrict__ Mo, float* __restrict__ Lo)
{
    int b = blockIdx.x, h = blockIdx.y;
    int tid = threadIdx.x;
    const float* row = S + ((size_t)h * BQ_ + b) * NC_;
    float m = -1e30f, l = 0.f;
    for (int i = tid; i < NC_; i += 256) {
        float x = row[i];
        float mn = fmaxf(m, x);
        l = l * expf(m - mn) + expf(x - mn);
        m = mn;
    }
    __shared__ float sm[256], sl[256];
    sm[tid] = m; sl[tid] = l; __syncthreads();
    for (int st = 128; st > 0; st >>= 1) {
        if (tid < st) {
            float m2 = sm[tid + st], l2 = sl[tid + st];
            float mn = fmaxf(sm[tid], m2);
            sl[tid] = sl[tid] * expf(sm[tid] - mn) + l2 * expf(m2 - mn);
            sm[tid] = mn;
        }
        __syncthreads();
    }
    if (tid == 0) { Mo[b * H_ + h] = sm[0]; Lo[b * H_ + h] = sl[0]; }
}

// ---------------- final fused: cos / euclid / learned + fusion MLP + sigmoid ----
__global__ __launch_bounds__(256) void final_kernel(
    const float* __restrict__ GQK, const float* __restrict__ S,
    const float* __restrict__ qsq, const float* __restrict__ qrn,
    const float* __restrict__ ksq, const float* __restrict__ krn,
    const float* __restrict__ Mst, const float* __restrict__ Lst,
    const float* __restrict__ fw1, const float* __restrict__ fb1,
    const float* __restrict__ fw2, const float* __restrict__ fb2,
    const float* __restrict__ temp, float* __restrict__ out)
{
    __shared__ float sW1[192], sB1[64], sW2[64];
    __shared__ float sM[8], sIL[8];
    __shared__ float sb2, sET, sQsq, sQrn;
    int tid = threadIdx.x;
    int b = blockIdx.y;
    if (tid < 192) sW1[tid] = fw1[tid];
    if (tid < 64) { sB1[tid] = fb1[tid]; sW2[tid] = fw2[tid]; }
    if (tid < 8)  { sM[tid] = Mst[b * H_ + tid]; sIL[tid] = 1.f / Lst[b * H_ + tid]; }
    if (tid == 0) { sb2 = fb2[0]; sET = expf(temp[0]); sQsq = qsq[b]; sQrn = qrn[b]; }
    __syncthreads();

    int n = blockIdx.x * 256 + tid;
    float g = GQK[(size_t)b * NC_ + n];
    float cosv = g * sQrn * krn[n] * sET;
    float d2 = fmaxf(sQsq + ksq[n] - 2.f * g, 0.f);
    float euc = 1.f / (1.f + sqrtf(d2));
    float lsum = 0.f;
    #pragma unroll
    for (int h = 0; h < 8; h++) {
        float s = S[((size_t)h * BQ_ + b) * NC_ + n];
        lsum += expf(s - sM[h]) * sIL[h];
    }
    float learned = 0.125f * lsum;

    float logit = sb2;
    #pragma unroll 16
    for (int j = 0; j < 64; j++) {
        float hv = cosv * sW1[j] + euc * sW1[64 + j] + learned * sW1[128 + j] + sB1[j];
        hv = fmaxf(hv, 0.f);
        logit += hv * sW2[j];
    }
    out[(size_t)b * NC_ + n] = 1.f / (1.f + expf(-logit));
}

// ------------------------------- launcher -------------------------------------
extern "C" void kernel_launch(void* const* d_in, const int* in_sizes, int n_in,
                              void* d_out, int out_size)
{
    const float* qf   = (const float*)d_in[0];
    const float* cf   = (const float*)d_in[1];
    const float* temp = (const float*)d_in[2];
    const float* q_w1 = (const float*)d_in[3];
    const float* q_b1 = (const float*)d_in[4];
    const float* q_g  = (const float*)d_in[5];
    const float* q_be = (const float*)d_in[6];
    const float* q_w2 = (const float*)d_in[7];
    const float* q_b2 = (const float*)d_in[8];
    const float* k_w1 = (const float*)d_in[9];
    const float* k_b1 = (const float*)d_in[10];
    const float* k_g  = (const float*)d_in[11];
    const float* k_be = (const float*)d_in[12];
    const float* k_w2 = (const float*)d_in[13];
    const float* k_b2 = (const float*)d_in[14];
    const float* wq   = (const float*)d_in[15];
    const float* bq   = (const float*)d_in[16];
    const float* wk   = (const float*)d_in[17];
    const float* bk   = (const float*)d_in[18];
    const float* fw1  = (const float*)d_in[19];
    const float* fb1  = (const float*)d_in[20];
    const float* fw2  = (const float*)d_in[21];
    const float* fb2  = (const float*)d_in[22];

    float *buf, *KP, *KH, *qbuf, *QP, *QH, *GQK, *S;
    float *ksq, *krn, *qsq, *qrn, *Mst, *Lst;
    cudaGetSymbolAddress((void**)&buf,  g_buf);
    cudaGetSymbolAddress((void**)&KP,   g_KP);
    cudaGetSymbolAddress((void**)&KH,   g_KH);
    cudaGetSymbolAddress((void**)&qbuf, g_qbuf);
    cudaGetSymbolAddress((void**)&QP,   g_QP);
    cudaGetSymbolAddress((void**)&QH,   g_QH);
    cudaGetSymbolAddress((void**)&GQK,  g_GQK);
    cudaGetSymbolAddress((void**)&S,    g_S);
    cudaGetSymbolAddress((void**)&ksq,  g_ksq);
    cudaGetSymbolAddress((void**)&krn,  g_krn);
    cudaGetSymbolAddress((void**)&qsq,  g_qsq);
    cudaGetSymbolAddress((void**)&qrn,  g_qrn);
    cudaGetSymbolAddress((void**)&Mst,  g_m);
    cudaGetSymbolAddress((void**)&Lst,  g_l);

    // ---- key path ----
    sgemm_nn_bias<<<dim3(D_/128, NC_/128), 256>>>(cf, k_w1, k_b1, buf, NC_, D_, D_);
    ln_gelu_kernel<<<NC_, 256>>>(buf, k_g, k_be);
    sgemm_nn_bias<<<dim3(D_/128, NC_/128), 256>>>(buf, k_w2, k_b2, KP, NC_, D_, D_);
    sgemm_nn_bias<<<dim3(D_/128, NC_/128), 256>>>(KP, wk, bk, KH, NC_, D_, D_);
    row_stats_kernel<<<NC_, 256>>>(KP, ksq, krn);

    // ---- query path ----
    sgemm_nn_bias<<<dim3(D_/128, BQ_/128), 256>>>(qf, q_w1, q_b1, qbuf, BQ_, D_, D_);
    ln_gelu_kernel<<<BQ_, 256>>>(qbuf, q_g, q_be);
    sgemm_nn_bias<<<dim3(D_/128, BQ_/128), 256>>>(qbuf, q_w2, q_b2, QP, BQ_, D_, D_);
    sgemm_nn_bias<<<dim3(D_/128, BQ_/128), 256>>>(QP, wq, bq, QH, BQ_, D_, D_);
    row_stats_kernel<<<BQ_, 256>>>(QP, qsq, qrn);

    // ---- pairwise ----
    sgemm_nt<<<dim3(NC_/128, BQ_/128, 1), 256>>>(
        QP, KP, GQK, BQ_, NC_, D_, D_, D_, 0, (size_t)0, 1.f);
    sgemm_nt<<<dim3(NC_/128, BQ_/128, H_), 256>>>(
        QH, KH, S, BQ_, NC_, HD_, D_, D_, HD_, (size_t)BQ_ * NC_,
        0.08838834764831845f /* 1/sqrt(128) */);
    softmax_stats_kernel<<<dim3(BQ_, H_), 256>>>(S, Mst, Lst);
    final_kernel<<<dim3(NC_/256, BQ_), 256>>>(
        GQK, S, qsq, qrn, ksq, krn, Mst, Lst, fw1, fb1, fw2, fb2, temp, (float*)d_out);
}

// round 7
// speedup vs baseline: 2.7856x; 2.7856x over previous
#include <cuda_runtime.h>
#include <math.h>
#include <stdint.h>

#define D_   1024
#define BQ_  1024
#define NC_  16384
#define H_   8
#define HD_  128

// ---------------- scratch (device globals: allocation-free) ----------------
__device__ float g_buf [NC_ * D_];
__device__ float g_KP  [NC_ * D_];
__device__ float g_KH  [NC_ * D_];
__device__ float g_qbuf[BQ_ * D_];
__device__ float g_QP  [BQ_ * D_];
__device__ float g_QH  [BQ_ * D_];
__device__ float g_GQK [(size_t)BQ_ * NC_];
__device__ float g_S   [(size_t)H_ * BQ_ * NC_];
__device__ float g_Wt  [6 * (size_t)D_ * D_];      // transposed weights
__device__ float g_ksq [NC_], g_krn[NC_];
__device__ float g_qsq [BQ_], g_qrn[BQ_];
__device__ float g_m   [BQ_ * H_], g_l[BQ_ * H_];

// ====================== warp-level MMA helpers (tf32, legacy path) ==========
__device__ __forceinline__ uint32_t s2u(const void* p) {
    uint32_t a;
    asm("{ .reg .u64 t; cvta.to.shared.u64 t, %1; cvt.u32.u64 %0, t; }"
        : "=r"(a) : "l"(p));
    return a;
}
__device__ __forceinline__ void ldsm4(uint32_t* r, uint32_t addr) {
    asm volatile("ldmatrix.sync.aligned.m8n8.x4.shared.b16 {%0,%1,%2,%3}, [%4];"
                 : "=r"(r[0]), "=r"(r[1]), "=r"(r[2]), "=r"(r[3]) : "r"(addr));
}
__device__ __forceinline__ void mma8(float* c, const uint32_t* a, const uint32_t* b) {
    asm volatile(
        "mma.sync.aligned.m16n8k8.row.col.f32.tf32.tf32.f32 "
        "{%0,%1,%2,%3}, {%4,%5,%6,%7}, {%8,%9}, {%0,%1,%2,%3};"
        : "+f"(c[0]), "+f"(c[1]), "+f"(c[2]), "+f"(c[3])
        : "r"(a[0]), "r"(a[1]), "r"(a[2]), "r"(a[3]), "r"(b[0]), "r"(b[1]));
}

// ============ tf32 NT GEMM: C = scale * A[M,K] @ B[N,K]^T + bias ============
// CTA tile 128x128, K-chunk 32. 8 warps as 2(m) x 4(n), warp tile 64x32.
// Single smem buffer + register prefetch of the next chunk (LDG issued before
// compute, STS after). No mbarriers, no TMEM, no dynamic smem.
// z-dim heads: koff = z*koffz on A and B; C += z*zStrideC.
__global__ __launch_bounds__(256) void mma_gemm_nt(
    const float* __restrict__ A, const float* __restrict__ B,
    const float* __restrict__ bias, float* __restrict__ C,
    int K, int lda, int ldb, int ldc,
    int koffz, size_t zStrideC, float scale)
{
    __shared__ __align__(1024) char smem[32768];   // A 16KB + B 16KB
    __shared__ float sBias[128];

    const int tid  = threadIdx.x;
    const int lane = tid & 31;
    const int wid  = tid >> 5;
    const int wm   = wid & 1;          // 0..1
    const int wn   = wid >> 1;         // 0..3
    const int m0   = wm * 64;
    const int n0   = wn * 32;
    const int bm   = blockIdx.y * 128;
    const int bn   = blockIdx.x * 128;
    const int z    = blockIdx.z;
    const int koff = z * koffz;

    if (tid < 128) sBias[tid] = bias ? __ldg(&bias[bn + tid]) : 0.f;

    const uint32_t baseA = s2u(smem);
    const uint32_t baseB = baseA + 16384;

    // per-lane ldmatrix addressing (fragment-layout derivation in notes)
    const uint32_t mask  = (uint32_t)(lane & 7) << 4;      // swizzle xor (row%8)<<4
    const int  rowa  = ((lane >> 3) & 1) * 8 + (lane & 7);
    const uint32_t colA0 = ((lane >> 4) & 1) ? 16u : 0u;
    uint32_t aAddr[4];
    #pragma unroll
    for (int mf = 0; mf < 4; mf++)
        aAddr[mf] = baseA + (uint32_t)(m0 + mf * 16 + rowa) * 128u;
    uint32_t bAddr[2];
    #pragma unroll
    for (int p = 0; p < 2; p++) {
        int rowB = n0 + (2 * p + ((lane >> 4) & 1)) * 8 + (lane & 7);
        bAddr[p] = baseB + (uint32_t)rowB * 128u;
    }
    const uint32_t colB0 = (uint32_t)((lane >> 3) & 1) * 16u;

    // gmem loader mapping: thread covers 4 float4 per tile per chunk
    const float* Ab = A + (size_t)bm * lda + koff;
    const float* Bb = B + (size_t)bn * ldb + koff;

    float acc[4][4][4];
    #pragma unroll
    for (int i = 0; i < 4; i++)
        #pragma unroll
        for (int j = 0; j < 4; j++)
            #pragma unroll
            for (int k = 0; k < 4; k++) acc[i][j][k] = 0.f;

    const int NIT = K >> 5;
    float4 rA[4], rB[4];

    // prolog: chunk 0 -> regs -> smem
    #pragma unroll
    for (int i = 0; i < 4; i++) {
        int f = tid + i * 256, row = f >> 3, c = f & 7;
        rA[i] = *(const float4*)&Ab[(size_t)row * lda + c * 4];
        rB[i] = *(const float4*)&Bb[(size_t)row * ldb + c * 4];
    }
    #pragma unroll
    for (int i = 0; i < 4; i++) {
        int f = tid + i * 256, row = f >> 3, c = f & 7;
        uint32_t off = ((uint32_t)(row * 128 + c * 16)) ^ ((uint32_t)(row & 7) << 4);
        *(float4*)(smem + off)         = rA[i];
        *(float4*)(smem + 16384 + off) = rB[i];
    }
    __syncthreads();

    for (int it = 0; it < NIT; ++it) {
        const bool more = (it + 1 < NIT);
        if (more) {
            int k0n = (it + 1) * 32;
            #pragma unroll
            for (int i = 0; i < 4; i++) {
                int f = tid + i * 256, row = f >> 3, c = f & 7;
                rA[i] = *(const float4*)&Ab[(size_t)row * lda + k0n + c * 4];
                rB[i] = *(const float4*)&Bb[(size_t)row * ldb + k0n + c * 4];
            }
        }
        // compute chunk 'it' from smem
        #pragma unroll
        for (int ks = 0; ks < 4; ks++) {
            uint32_t b[2][4];
            uint32_t offB = (colB0 + (uint32_t)ks * 32u) ^ mask;
            ldsm4(b[0], bAddr[0] + offB);
            ldsm4(b[1], bAddr[1] + offB);
            uint32_t a[4][4];
            uint32_t offA = (colA0 + (uint32_t)ks * 32u) ^ mask;
            #pragma unroll
            for (int mf = 0; mf < 4; mf++) ldsm4(a[mf], aAddr[mf] + offA);
            #pragma unroll
            for (int mf = 0; mf < 4; mf++) {
                mma8(acc[mf][0], a[mf], &b[0][0]);
                mma8(acc[mf][1], a[mf], &b[0][2]);
                mma8(acc[mf][2], a[mf], &b[1][0]);
                mma8(acc[mf][3], a[mf], &b[1][2]);
            }
        }
        __syncthreads();
        if (more) {
            #pragma unroll
            for (int i = 0; i < 4; i++) {
                int f = tid + i * 256, row = f >> 3, c = f & 7;
                uint32_t off = ((uint32_t)(row * 128 + c * 16)) ^ ((uint32_t)(row & 7) << 4);
                *(float4*)(smem + off)         = rA[i];
                *(float4*)(smem + 16384 + off) = rB[i];
            }
            __syncthreads();
        }
    }

    // epilogue: scale + bias, float2 stores
    float* Cz = C + (size_t)z * zStrideC;
    #pragma unroll
    for (int mf = 0; mf < 4; mf++) {
        int r0 = bm + m0 + mf * 16 + (lane >> 2);
        #pragma unroll
        for (int nf = 0; nf < 4; nf++) {
            int cl = n0 + nf * 8 + (lane & 3) * 2;
            float b0 = sBias[cl], b1 = sBias[cl + 1];
            float2 v0, v1;
            v0.x = acc[mf][nf][0] * scale + b0;
            v0.y = acc[mf][nf][1] * scale + b1;
            v1.x = acc[mf][nf][2] * scale + b0;
            v1.y = acc[mf][nf][3] * scale + b1;
            *(float2*)&Cz[(size_t)r0 * ldc + bn + cl]       = v0;
            *(float2*)&Cz[(size_t)(r0 + 8) * ldc + bn + cl] = v1;
        }
    }
}

// ---------------- 1024x1024 transpose (for weights -> NT form) ----------------
__global__ __launch_bounds__(256) void transpose_k(
    const float* __restrict__ in, float* __restrict__ out)
{
    __shared__ float t[32][33];
    int x  = blockIdx.x * 32 + threadIdx.x;
    int y0 = blockIdx.y * 32;
    #pragma unroll
    for (int j = threadIdx.y; j < 32; j += 8)
        t[j][threadIdx.x] = in[(size_t)(y0 + j) * D_ + x];
    __syncthreads();
    int x2 = blockIdx.y * 32 + threadIdx.x;
    int y2 = blockIdx.x * 32;
    #pragma unroll
    for (int j = threadIdx.y; j < 32; j += 8)
        out[(size_t)(y2 + j) * D_ + x2] = t[threadIdx.x][j];
}

// ---------------- LayerNorm + exact GELU, in place ----------------
__global__ __launch_bounds__(256) void ln_gelu_kernel(
    float* __restrict__ X, const float* __restrict__ g, const float* __restrict__ be)
{
    __shared__ float sh[256];
    int row = blockIdx.x;
    float* xr = X + (size_t)row * D_;
    float v[4]; float s = 0.f, s2 = 0.f;
    #pragma unroll
    for (int i = 0; i < 4; i++) {
        int c = threadIdx.x + i * 256;
        v[i] = xr[c]; s += v[i]; s2 += v[i] * v[i];
    }
    sh[threadIdx.x] = s; __syncthreads();
    for (int st = 128; st > 0; st >>= 1) {
        if (threadIdx.x < st) sh[threadIdx.x] += sh[threadIdx.x + st];
        __syncthreads();
    }
    float mean = sh[0] * (1.f / D_); __syncthreads();
    sh[threadIdx.x] = s2; __syncthreads();
    for (int st = 128; st > 0; st >>= 1) {
        if (threadIdx.x < st) sh[threadIdx.x] += sh[threadIdx.x + st];
        __syncthreads();
    }
    float var  = sh[0] * (1.f / D_) - mean * mean;
    float rstd = rsqrtf(var + 1e-5f);
    #pragma unroll
    for (int i = 0; i < 4; i++) {
        int c = threadIdx.x + i * 256;
        float y = (v[i] - mean) * rstd * g[c] + be[c];
        xr[c] = 0.5f * y * (1.f + erff(y * 0.7071067811865475f));
    }
}

// ---------------- per-row sum of squares + reciprocal norm ----------------
__global__ __launch_bounds__(256) void row_stats_kernel(
    const float* __restrict__ X, float* __restrict__ sq, float* __restrict__ rn)
{
    __shared__ float sh[256];
    int row = blockIdx.x;
    const float* xr = X + (size_t)row * D_;
    float s2 = 0.f;
    #pragma unroll
    for (int i = 0; i < 4; i++) { float v = xr[threadIdx.x + i * 256]; s2 += v * v; }
    sh[threadIdx.x] = s2; __syncthreads();
    for (int st = 128; st > 0; st >>= 1) {
        if (threadIdx.x < st) sh[threadIdx.x] += sh[threadIdx.x + st];
        __syncthreads();
    }
    if (threadIdx.x == 0) { sq[row] = sh[0]; rn[row] = rsqrtf(sh[0]); }
}

// ---------------- softmax stats per (b,h) ----------------
__global__ __launch_bounds__(256) void softmax_stats_kernel(
    const float* __restrict__ S, float* __restrict__ Mo, float* __restrict__ Lo)
{
    int b = blockIdx.x, h = blockIdx.y;
    int tid = threadIdx.x;
    const float* row = S + ((size_t)h * BQ_ + b) * NC_;
    float m = -1e30f, l = 0.f;
    for (int i = tid; i < NC_; i += 256) {
        float x = row[i];
        float mn = fmaxf(m, x);
        l = l * expf(m - mn) + expf(x - mn);
        m = mn;
    }
    __shared__ float sm[256], sl[256];
    sm[tid] = m; sl[tid] = l; __syncthreads();
    for (int st = 128; st > 0; st >>= 1) {
        if (tid < st) {
            float m2 = sm[tid + st], l2 = sl[tid + st];
            float mn = fmaxf(sm[tid], m2);
            sl[tid] = sl[tid] * expf(sm[tid] - mn) + l2 * expf(m2 - mn);
            sm[tid] = mn;
        }
        __syncthreads();
    }
    if (tid == 0) { Mo[b * H_ + h] = sm[0]; Lo[b * H_ + h] = sl[0]; }
}

// ---------------- final fused: features + fusion MLP + sigmoid ----------------
__global__ __launch_bounds__(256) void final_kernel(
    const float* __restrict__ GQK, const float* __restrict__ S,
    const float* __restrict__ qsq, const float* __restrict__ qrn,
    const float* __restrict__ ksq, const float* __restrict__ krn,
    const float* __restrict__ Mst, const float* __restrict__ Lst,
    const float* __restrict__ fw1, const float* __restrict__ fb1,
    const float* __restrict__ fw2, const float* __restrict__ fb2,
    const float* __restrict__ temp, float* __restrict__ out)
{
    __shared__ float sW1[192], sB1[64], sW2[64];
    __shared__ float sM[8], sIL[8];
    __shared__ float sb2, sET, sQsq, sQrn;
    int tid = threadIdx.x;
    int b = blockIdx.y;
    if (tid < 192) sW1[tid] = fw1[tid];
    if (tid < 64) { sB1[tid] = fb1[tid]; sW2[tid] = fw2[tid]; }
    if (tid < 8)  { sM[tid] = Mst[b * H_ + tid]; sIL[tid] = 1.f / Lst[b * H_ + tid]; }
    if (tid == 0) { sb2 = fb2[0]; sET = expf(temp[0]); sQsq = qsq[b]; sQrn = qrn[b]; }
    __syncthreads();

    int n = blockIdx.x * 256 + tid;
    float g = GQK[(size_t)b * NC_ + n];
    float cosv = g * sQrn * krn[n] * sET;
    float d2 = fmaxf(sQsq + ksq[n] - 2.f * g, 0.f);
    float euc = 1.f / (1.f + sqrtf(d2));
    float lsum = 0.f;
    #pragma unroll
    for (int h = 0; h < 8; h++) {
        float s = S[((size_t)h * BQ_ + b) * NC_ + n];
        lsum += expf(s - sM[h]) * sIL[h];
    }
    float learned = 0.125f * lsum;

    float logit = sb2;
    #pragma unroll 16
    for (int j = 0; j < 64; j++) {
        float hv = cosv * sW1[j] + euc * sW1[64 + j] + learned * sW1[128 + j] + sB1[j];
        hv = fmaxf(hv, 0.f);
        logit += hv * sW2[j];
    }
    out[(size_t)b * NC_ + n] = 1.f / (1.f + expf(-logit));
}

// ------------------------------- launcher -------------------------------------
extern "C" void kernel_launch(void* const* d_in, const int* in_sizes, int n_in,
                              void* d_out, int out_size)
{
    const float* qf   = (const float*)d_in[0];
    const float* cf   = (const float*)d_in[1];
    const float* temp = (const float*)d_in[2];
    const float* q_w1 = (const float*)d_in[3];
    const float* q_b1 = (const float*)d_in[4];
    const float* q_g  = (const float*)d_in[5];
    const float* q_be = (const float*)d_in[6];
    const float* q_w2 = (const float*)d_in[7];
    const float* q_b2 = (const float*)d_in[8];
    const float* k_w1 = (const float*)d_in[9];
    const float* k_b1 = (const float*)d_in[10];
    const float* k_g  = (const float*)d_in[11];
    const float* k_be = (const float*)d_in[12];
    const float* k_w2 = (const float*)d_in[13];
    const float* k_b2 = (const float*)d_in[14];
    const float* wq   = (const float*)d_in[15];
    const float* bq   = (const float*)d_in[16];
    const float* wk   = (const float*)d_in[17];
    const float* bk   = (const float*)d_in[18];
    const float* fw1  = (const float*)d_in[19];
    const float* fb1  = (const float*)d_in[20];
    const float* fw2  = (const float*)d_in[21];
    const float* fb2  = (const float*)d_in[22];

    float *buf, *KP, *KH, *qbuf, *QP, *QH, *GQK, *S, *Wt;
    float *ksq, *krn, *qsq, *qrn, *Mst, *Lst;
    cudaGetSymbolAddress((void**)&buf,  g_buf);
    cudaGetSymbolAddress((void**)&KP,   g_KP);
    cudaGetSymbolAddress((void**)&KH,   g_KH);
    cudaGetSymbolAddress((void**)&qbuf, g_qbuf);
    cudaGetSymbolAddress((void**)&QP,   g_QP);
    cudaGetSymbolAddress((void**)&QH,   g_QH);
    cudaGetSymbolAddress((void**)&GQK,  g_GQK);
    cudaGetSymbolAddress((void**)&S,    g_S);
    cudaGetSymbolAddress((void**)&Wt,   g_Wt);
    cudaGetSymbolAddress((void**)&ksq,  g_ksq);
    cudaGetSymbolAddress((void**)&krn,  g_krn);
    cudaGetSymbolAddress((void**)&qsq,  g_qsq);
    cudaGetSymbolAddress((void**)&qrn,  g_qrn);
    cudaGetSymbolAddress((void**)&Mst,  g_m);
    cudaGetSymbolAddress((void**)&Lst,  g_l);

    static const size_t WSZ = (size_t)D_ * D_;
    float* Wt_kw1 = Wt + 0 * WSZ;
    float* Wt_kw2 = Wt + 1 * WSZ;
    float* Wt_wk  = Wt + 2 * WSZ;
    float* Wt_qw1 = Wt + 3 * WSZ;
    float* Wt_qw2 = Wt + 4 * WSZ;
    float* Wt_wq  = Wt + 5 * WSZ;

    // ---- weight transposes (W[K,N] -> Wt[N,K]) ----
    dim3 tb(32, 8), tg(32, 32);
    transpose_k<<<tg, tb>>>(k_w1, Wt_kw1);
    transpose_k<<<tg, tb>>>(k_w2, Wt_kw2);
    transpose_k<<<tg, tb>>>(wk,   Wt_wk);
    transpose_k<<<tg, tb>>>(q_w1, Wt_qw1);
    transpose_k<<<tg, tb>>>(q_w2, Wt_qw2);
    transpose_k<<<tg, tb>>>(wq,   Wt_wq);

    // ---- key path ----
    mma_gemm_nt<<<dim3(D_/128, NC_/128, 1), 256>>>(
        cf, Wt_kw1, k_b1, buf, D_, D_, D_, D_, 0, (size_t)0, 1.f);
    ln_gelu_kernel<<<NC_, 256>>>(buf, k_g, k_be);
    mma_gemm_nt<<<dim3(D_/128, NC_/128, 1), 256>>>(
        buf, Wt_kw2, k_b2, KP, D_, D_, D_, D_, 0, (size_t)0, 1.f);
    mma_gemm_nt<<<dim3(D_/128, NC_/128, 1), 256>>>(
        KP, Wt_wk, bk, KH, D_, D_, D_, D_, 0, (size_t)0, 1.f);
    row_stats_kernel<<<NC_, 256>>>(KP, ksq, krn);

    // ---- query path ----
    mma_gemm_nt<<<dim3(D_/128, BQ_/128, 1), 256>>>(
        qf, Wt_qw1, q_b1, qbuf, D_, D_, D_, D_, 0, (size_t)0, 1.f);
    ln_gelu_kernel<<<BQ_, 256>>>(qbuf, q_g, q_be);
    mma_gemm_nt<<<dim3(D_/128, BQ_/128, 1), 256>>>(
        qbuf, Wt_qw2, q_b2, QP, D_, D_, D_, D_, 0, (size_t)0, 1.f);
    mma_gemm_nt<<<dim3(D_/128, BQ_/128, 1), 256>>>(
        QP, Wt_wq, bq, QH, D_, D_, D_, D_, 0, (size_t)0, 1.f);
    row_stats_kernel<<<BQ_, 256>>>(QP, qsq, qrn);

    // ---- pairwise ----
    mma_gemm_nt<<<dim3(NC_/128, BQ_/128, 1), 256>>>(
        QP, KP, (const float*)nullptr, GQK, D_, D_, D_, NC_, 0, (size_t)0, 1.f);
    mma_gemm_nt<<<dim3(NC_/128, BQ_/128, H_), 256>>>(
        QH, KH, (const float*)nullptr, S, HD_, D_, D_, NC_, HD_, (size_t)BQ_ * NC_,
        0.08838834764831845f /* 1/sqrt(128) */);

    softmax_stats_kernel<<<dim3(BQ_, H_), 256>>>(S, Mst, Lst);
    final_kernel<<<dim3(NC_/256, BQ_), 256>>>(
        GQK, S, qsq, qrn, ksq, krn, Mst, Lst, fw1, fb1, fw2, fb2, temp, (float*)d_out);
}

// round 9
// speedup vs baseline: 2.7902x; 1.0017x over previous
#include <cuda_runtime.h>
#include <math.h>
#include <stdint.h>

#define D_   1024
#define BQ_  1024
#define NC_  16384
#define H_   8
#define HD_  128

// ---------------- scratch (device globals: allocation-free) ----------------
__device__ float g_buf [NC_ * D_];
__device__ float g_KP  [NC_ * D_];
__device__ float g_KH  [NC_ * D_];
__device__ float g_qbuf[BQ_ * D_];
__device__ float g_QP  [BQ_ * D_];
__device__ float g_QH  [BQ_ * D_];
__device__ float g_GQK [(size_t)BQ_ * NC_];
__device__ float g_S   [(size_t)H_ * BQ_ * NC_];
__device__ float g_Wt  [6 * (size_t)D_ * D_];      // transposed weights
__device__ float g_ksq [NC_], g_krn[NC_];
__device__ float g_qsq [BQ_], g_qrn[BQ_];
__device__ float g_m   [BQ_ * H_], g_l[BQ_ * H_];

// ====================== warp-level MMA helpers (tf32, legacy path) ==========
__device__ __forceinline__ uint32_t s2u(const void* p) {
    uint32_t a;
    asm("{ .reg .u64 t; cvta.to.shared.u64 t, %1; cvt.u32.u64 %0, t; }"
        : "=r"(a) : "l"(p));
    return a;
}
__device__ __forceinline__ void ldsm4(uint32_t* r, uint32_t addr) {
    asm volatile("ldmatrix.sync.aligned.m8n8.x4.shared.b16 {%0,%1,%2,%3}, [%4];"
                 : "=r"(r[0]), "=r"(r[1]), "=r"(r[2]), "=r"(r[3]) : "r"(addr));
}
__device__ __forceinline__ void mma8(float* c, const uint32_t* a, const uint32_t* b) {
    asm volatile(
        "mma.sync.aligned.m16n8k8.row.col.f32.tf32.tf32.f32 "
        "{%0,%1,%2,%3}, {%4,%5,%6,%7}, {%8,%9}, {%0,%1,%2,%3};"
        : "+f"(c[0]), "+f"(c[1]), "+f"(c[2]), "+f"(c[3])
        : "r"(a[0]), "r"(a[1]), "r"(a[2]), "r"(a[3]), "r"(b[0]), "r"(b[1]));
}

// ============ tf32 NT GEMM: C = scale * A[M,K] @ B[N,K]^T + bias ============
// CTA tile 128x128, K-chunk 32. 8 warps as 2(m) x 4(n), warp tile 64x32.
// Single smem buffer + register prefetch of the next chunk (LDG issued before
// compute, STS after). Static smem only — no attributes, no dynamic smem.
// z-dim heads: koff = z*koffz on A and B; C += z*zStrideC.
__global__ __launch_bounds__(256) void mma_gemm_nt(
    const float* __restrict__ A, const float* __restrict__ B,
    const float* __restrict__ bias, float* __restrict__ C,
    int K, int lda, int ldb, int ldc,
    int koffz, size_t zStrideC, float scale)
{
    __shared__ __align__(1024) char smem[32768];   // A 16KB + B 16KB
    __shared__ float sBias[128];

    const int tid  = threadIdx.x;
    const int lane = tid & 31;
    const int wid  = tid >> 5;
    const int wm   = wid & 1;          // 0..1
    const int wn   = wid >> 1;         // 0..3
    const int m0   = wm * 64;
    const int n0   = wn * 32;
    const int bm   = blockIdx.y * 128;
    const int bn   = blockIdx.x * 128;
    const int z    = blockIdx.z;
    const int koff = z * koffz;

    if (tid < 128) sBias[tid] = bias ? __ldg(&bias[bn + tid]) : 0.f;

    const uint32_t baseA = s2u(smem);
    const uint32_t baseB = baseA + 16384;

    // per-lane ldmatrix addressing (fragment-layout derivation in notes)
    const uint32_t mask  = (uint32_t)(lane & 7) << 4;      // swizzle xor (row%8)<<4
    const int  rowa  = ((lane >> 3) & 1) * 8 + (lane & 7);
    const uint32_t colA0 = ((lane >> 4) & 1) ? 16u : 0u;
    uint32_t aAddr[4];
    #pragma unroll
    for (int mf = 0; mf < 4; mf++)
        aAddr[mf] = baseA + (uint32_t)(m0 + mf * 16 + rowa) * 128u;
    uint32_t bAddr[2];
    #pragma unroll
    for (int p = 0; p < 2; p++) {
        int rowB = n0 + (2 * p + ((lane >> 4) & 1)) * 8 + (lane & 7);
        bAddr[p] = baseB + (uint32_t)rowB * 128u;
    }
    const uint32_t colB0 = (uint32_t)((lane >> 3) & 1) * 16u;

    // gmem loader mapping: thread covers 4 float4 per tile per chunk
    const float* Ab = A + (size_t)bm * lda + koff;
    const float* Bb = B + (size_t)bn * ldb + koff;

    float acc[4][4][4];
    #pragma unroll
    for (int i = 0; i < 4; i++)
        #pragma unroll
        for (int j = 0; j < 4; j++)
            #pragma unroll
            for (int k = 0; k < 4; k++) acc[i][j][k] = 0.f;

    const int NIT = K >> 5;
    float4 rA[4], rB[4];

    // prolog: chunk 0 -> regs -> smem
    #pragma unroll
    for (int i = 0; i < 4; i++) {
        int f = tid + i * 256, row = f >> 3, c = f & 7;
        rA[i] = *(const float4*)&Ab[(size_t)row * lda + c * 4];
        rB[i] = *(const float4*)&Bb[(size_t)row * ldb + c * 4];
    }
    #pragma unroll
    for (int i = 0; i < 4; i++) {
        int f = tid + i * 256, row = f >> 3, c = f & 7;
        uint32_t off = ((uint32_t)(row * 128 + c * 16)) ^ ((uint32_t)(row & 7) << 4);
        *(float4*)(smem + off)         = rA[i];
        *(float4*)(smem + 16384 + off) = rB[i];
    }
    __syncthreads();

    for (int it = 0; it < NIT; ++it) {
        const bool more = (it + 1 < NIT);
        if (more) {
            int k0n = (it + 1) * 32;
            #pragma unroll
            for (int i = 0; i < 4; i++) {
                int f = tid + i * 256, row = f >> 3, c = f & 7;
                rA[i] = *(const float4*)&Ab[(size_t)row * lda + k0n + c * 4];
                rB[i] = *(const float4*)&Bb[(size_t)row * ldb + k0n + c * 4];
            }
        }
        // compute chunk 'it' from smem
        #pragma unroll
        for (int ks = 0; ks < 4; ks++) {
            uint32_t b[2][4];
            uint32_t offB = (colB0 + (uint32_t)ks * 32u) ^ mask;
            ldsm4(b[0], bAddr[0] + offB);
            ldsm4(b[1], bAddr[1] + offB);
            uint32_t a[4][4];
            uint32_t offA = (colA0 + (uint32_t)ks * 32u) ^ mask;
            #pragma unroll
            for (int mf = 0; mf < 4; mf++) ldsm4(a[mf], aAddr[mf] + offA);
            #pragma unroll
            for (int mf = 0; mf < 4; mf++) {
                mma8(acc[mf][0], a[mf], &b[0][0]);
                mma8(acc[mf][1], a[mf], &b[0][2]);
                mma8(acc[mf][2], a[mf], &b[1][0]);
                mma8(acc[mf][3], a[mf], &b[1][2]);
            }
        }
        __syncthreads();
        if (more) {
            #pragma unroll
            for (int i = 0; i < 4; i++) {
                int f = tid + i * 256, row = f >> 3, c = f & 7;
                uint32_t off = ((uint32_t)(row * 128 + c * 16)) ^ ((uint32_t)(row & 7) << 4);
                *(float4*)(smem + off)         = rA[i];
                *(float4*)(smem + 16384 + off) = rB[i];
            }
            __syncthreads();
        }
    }

    // epilogue: scale + bias, float2 stores
    float* Cz = C + (size_t)z * zStrideC;
    #pragma unroll
    for (int mf = 0; mf < 4; mf++) {
        int r0 = bm + m0 + mf * 16 + (lane >> 2);
        #pragma unroll
        for (int nf = 0; nf < 4; nf++) {
            int cl = n0 + nf * 8 + (lane & 3) * 2;
            float b0 = sBias[cl], b1 = sBias[cl + 1];
            float2 v0, v1;
            v0.x = acc[mf][nf][0] * scale + b0;
            v0.y = acc[mf][nf][1] * scale + b1;
            v1.x = acc[mf][nf][2] * scale + b0;
            v1.y = acc[mf][nf][3] * scale + b1;
            *(float2*)&Cz[(size_t)r0 * ldc + bn + cl]       = v0;
            *(float2*)&Cz[(size_t)(r0 + 8) * ldc + bn + cl] = v1;
        }
    }
}

// ---------------- 1024x1024 transpose (for weights -> NT form) ----------------
__global__ __launch_bounds__(256) void transpose_k(
    const float* __restrict__ in, float* __restrict__ out)
{
    __shared__ float t[32][33];
    int x  = blockIdx.x * 32 + threadIdx.x;
    int y0 = blockIdx.y * 32;
    #pragma unroll
    for (int j = threadIdx.y; j < 32; j += 8)
        t[j][threadIdx.x] = in[(size_t)(y0 + j) * D_ + x];
    __syncthreads();
    int x2 = blockIdx.y * 32 + threadIdx.x;
    int y2 = blockIdx.x * 32;
    #pragma unroll
    for (int j = threadIdx.y; j < 32; j += 8)
        out[(size_t)(y2 + j) * D_ + x2] = t[threadIdx.x][j];
}

// ---------------- LayerNorm + exact GELU, in place ----------------
__global__ __launch_bounds__(256) void ln_gelu_kernel(
    float* __restrict__ X, const float* __restrict__ g, const float* __restrict__ be)
{
    __shared__ float sh[256];
    int row = blockIdx.x;
    float* xr = X + (size_t)row * D_;
    float v[4]; float s = 0.f, s2 = 0.f;
    #pragma unroll
    for (int i = 0; i < 4; i++) {
        int c = threadIdx.x + i * 256;
        v[i] = xr[c]; s += v[i]; s2 += v[i] * v[i];
    }
    sh[threadIdx.x] = s; __syncthreads();
    for (int st = 128; st > 0; st >>= 1) {
        if (threadIdx.x < st) sh[threadIdx.x] += sh[threadIdx.x + st];
        __syncthreads();
    }
    float mean = sh[0] * (1.f / D_); __syncthreads();
    sh[threadIdx.x] = s2; __syncthreads();
    for (int st = 128; st > 0; st >>= 1) {
        if (threadIdx.x < st) sh[threadIdx.x] += sh[threadIdx.x + st];
        __syncthreads();
    }
    float var  = sh[0] * (1.f / D_) - mean * mean;
    float rstd = rsqrtf(var + 1e-5f);
    #pragma unroll
    for (int i = 0; i < 4; i++) {
        int c = threadIdx.x + i * 256;
        float y = (v[i] - mean) * rstd * g[c] + be[c];
        xr[c] = 0.5f * y * (1.f + erff(y * 0.7071067811865475f));
    }
}

// ---------------- per-row sum of squares + reciprocal norm ----------------
__global__ __launch_bounds__(256) void row_stats_kernel(
    const float* __restrict__ X, float* __restrict__ sq, float* __restrict__ rn)
{
    __shared__ float sh[256];
    int row = blockIdx.x;
    const float* xr = X + (size_t)row * D_;
    float s2 = 0.f;
    #pragma unroll
    for (int i = 0; i < 4; i++) { float v = xr[threadIdx.x + i * 256]; s2 += v * v; }
    sh[threadIdx.x] = s2; __syncthreads();
    for (int st = 128; st > 0; st >>= 1) {
        if (threadIdx.x < st) sh[threadIdx.x] += sh[threadIdx.x + st];
        __syncthreads();
    }
    if (threadIdx.x == 0) { sq[row] = sh[0]; rn[row] = rsqrtf(sh[0]); }
}

// ---------------- softmax stats per (b,h): two-pass (max, then sum-exp) --------
// Pass 2 re-reads the 64KB row from L2 (hot). 1 exp per element vs 2 for the
// online branchless update; __expf = single MUFU.EX2 path.
__global__ __launch_bounds__(256) void softmax_stats_kernel(
    const float* __restrict__ S, float* __restrict__ Mo, float* __restrict__ Lo)
{
    int b = blockIdx.x, h = blockIdx.y;
    int tid = threadIdx.x;
    const float4* row = (const float4*)(S + ((size_t)h * BQ_ + b) * NC_);
    __shared__ float sm[256], sl[256];

    float m = -1e30f;
    for (int i = tid; i < NC_ / 4; i += 256) {
        float4 v = row[i];
        m = fmaxf(m, fmaxf(fmaxf(v.x, v.y), fmaxf(v.z, v.w)));
    }
    sm[tid] = m; __syncthreads();
    for (int st = 128; st > 0; st >>= 1) {
        if (tid < st) sm[tid] = fmaxf(sm[tid], sm[tid + st]);
        __syncthreads();
    }
    m = sm[0];

    float l = 0.f;
    for (int i = tid; i < NC_ / 4; i += 256) {
        float4 v = row[i];
        l += __expf(v.x - m) + __expf(v.y - m) + __expf(v.z - m) + __expf(v.w - m);
    }
    sl[tid] = l; __syncthreads();
    for (int st = 128; st > 0; st >>= 1) {
        if (tid < st) sl[tid] += sl[tid + st];
        __syncthreads();
    }
    if (tid == 0) { Mo[b * H_ + h] = m; Lo[b * H_ + h] = sl[0]; }
}

// ---------------- final fused: features + fusion MLP + sigmoid ----------------
__global__ __launch_bounds__(256) void final_kernel(
    const float* __restrict__ GQK, const float* __restrict__ S,
    const float* __restrict__ qsq, const float* __restrict__ qrn,
    const float* __restrict__ ksq, const float* __restrict__ krn,
    const float* __restrict__ Mst, const float* __restrict__ Lst,
    const float* __restrict__ fw1, const float* __restrict__ fb1,
    const float* __restrict__ fw2, const float* __restrict__ fb2,
    const float* __restrict__ temp, float* __restrict__ out)
{
    __shared__ float sW1[192], sB1[64], sW2[64];
    __shared__ float sM[8], sIL[8];
    __shared__ float sb2, sET, sQsq, sQrn;
    int tid = threadIdx.x;
    int b = blockIdx.y;
    if (tid < 192) sW1[tid] = fw1[tid];
    if (tid < 64) { sB1[tid] = fb1[tid]; sW2[tid] = fw2[tid]; }
    if (tid < 8)  { sM[tid] = Mst[b * H_ + tid]; sIL[tid] = 1.f / Lst[b * H_ + tid]; }
    if (tid == 0) { sb2 = fb2[0]; sET = expf(temp[0]); sQsq = qsq[b]; sQrn = qrn[b]; }
    __syncthreads();

    int n = blockIdx.x * 256 + tid;
    float g = GQK[(size_t)b * NC_ + n];
    float cosv = g * sQrn * krn[n] * sET;
    float d2 = fmaxf(sQsq + ksq[n] - 2.f * g, 0.f);
    float euc = 1.f / (1.f + sqrtf(d2));
    float lsum = 0.f;
    #pragma unroll
    for (int h = 0; h < 8; h++) {
        float s = S[((size_t)h * BQ_ + b) * NC_ + n];
        lsum += __expf(s - sM[h]) * sIL[h];
    }
    float learned = 0.125f * lsum;

    float logit = sb2;
    #pragma unroll 16
    for (int j = 0; j < 64; j++) {
        float hv = cosv * sW1[j] + euc * sW1[64 + j] + learned * sW1[128 + j] + sB1[j];
        hv = fmaxf(hv, 0.f);
        logit += hv * sW2[j];
    }
    out[(size_t)b * NC_ + n] = 1.f / (1.f + __expf(-logit));
}

// ------------------------------- launcher -------------------------------------
extern "C" void kernel_launch(void* const* d_in, const int* in_sizes, int n_in,
                              void* d_out, int out_size)
{
    const float* qf   = (const float*)d_in[0];
    const float* cf   = (const float*)d_in[1];
    const float* temp = (const float*)d_in[2];
    const float* q_w1 = (const float*)d_in[3];
    const float* q_b1 = (const float*)d_in[4];
    const float* q_g  = (const float*)d_in[5];
    const float* q_be = (const float*)d_in[6];
    const float* q_w2 = (const float*)d_in[7];
    const float* q_b2 = (const float*)d_in[8];
    const float* k_w1 = (const float*)d_in[9];
    const float* k_b1 = (const float*)d_in[10];
    const float* k_g  = (const float*)d_in[11];
    const float* k_be = (const float*)d_in[12];
    const float* k_w2 = (const float*)d_in[13];
    const float* k_b2 = (const float*)d_in[14];
    const float* wq   = (const float*)d_in[15];
    const float* bq   = (const float*)d_in[16];
    const float* wk   = (const float*)d_in[17];
    const float* bk   = (const float*)d_in[18];
    const float* fw1  = (const float*)d_in[19];
    const float* fb1  = (const float*)d_in[20];
    const float* fw2  = (const float*)d_in[21];
    const float* fb2  = (const float*)d_in[22];

    float *buf, *KP, *KH, *qbuf, *QP, *QH, *GQK, *S, *Wt;
    float *ksq, *krn, *qsq, *qrn, *Mst, *Lst;
    cudaGetSymbolAddress((void**)&buf,  g_buf);
    cudaGetSymbolAddress((void**)&KP,   g_KP);
    cudaGetSymbolAddress((void**)&KH,   g_KH);
    cudaGetSymbolAddress((void**)&qbuf, g_qbuf);
    cudaGetSymbolAddress((void**)&QP,   g_QP);
    cudaGetSymbolAddress((void**)&QH,   g_QH);
    cudaGetSymbolAddress((void**)&GQK,  g_GQK);
    cudaGetSymbolAddress((void**)&S,    g_S);
    cudaGetSymbolAddress((void**)&Wt,   g_Wt);
    cudaGetSymbolAddress((void**)&ksq,  g_ksq);
    cudaGetSymbolAddress((void**)&krn,  g_krn);
    cudaGetSymbolAddress((void**)&qsq,  g_qsq);
    cudaGetSymbolAddress((void**)&qrn,  g_qrn);
    cudaGetSymbolAddress((void**)&Mst,  g_m);
    cudaGetSymbolAddress((void**)&Lst,  g_l);

    static const size_t WSZ = (size_t)D_ * D_;
    float* Wt_kw1 = Wt + 0 * WSZ;
    float* Wt_kw2 = Wt + 1 * WSZ;
    float* Wt_wk  = Wt + 2 * WSZ;
    float* Wt_qw1 = Wt + 3 * WSZ;
    float* Wt_qw2 = Wt + 4 * WSZ;
    float* Wt_wq  = Wt + 5 * WSZ;

    // ---- weight transposes (W[K,N] -> Wt[N,K]) ----
    dim3 tb(32, 8), tg(32, 32);
    transpose_k<<<tg, tb>>>(k_w1, Wt_kw1);
    transpose_k<<<tg, tb>>>(k_w2, Wt_kw2);
    transpose_k<<<tg, tb>>>(wk,   Wt_wk);
    transpose_k<<<tg, tb>>>(q_w1, Wt_qw1);
    transpose_k<<<tg, tb>>>(q_w2, Wt_qw2);
    transpose_k<<<tg, tb>>>(wq,   Wt_wq);

    // ---- key path ----
    mma_gemm_nt<<<dim3(D_/128, NC_/128, 1), 256>>>(
        cf, Wt_kw1, k_b1, buf, D_, D_, D_, D_, 0, (size_t)0, 1.f);
    ln_gelu_kernel<<<NC_, 256>>>(buf, k_g, k_be);
    mma_gemm_nt<<<dim3(D_/128, NC_/128, 1), 256>>>(
        buf, Wt_kw2, k_b2, KP, D_, D_, D_, D_, 0, (size_t)0, 1.f);
    mma_gemm_nt<<<dim3(D_/128, NC_/128, 1), 256>>>(
        KP, Wt_wk, bk, KH, D_, D_, D_, D_, 0, (size_t)0, 1.f);
    row_stats_kernel<<<NC_, 256>>>(KP, ksq, krn);

    // ---- query path ----
    mma_gemm_nt<<<dim3(D_/128, BQ_/128, 1), 256>>>(
        qf, Wt_qw1, q_b1, qbuf, D_, D_, D_, D_, 0, (size_t)0, 1.f);
    ln_gelu_kernel<<<BQ_, 256>>>(qbuf, q_g, q_be);
    mma_gemm_nt<<<dim3(D_/128, BQ_/128, 1), 256>>>(
        qbuf, Wt_qw2, q_b2, QP, D_, D_, D_, D_, 0, (size_t)0, 1.f);
    mma_gemm_nt<<<dim3(D_/128, BQ_/128, 1), 256>>>(
        QP, Wt_wq, bq, QH, D_, D_, D_, D_, 0, (size_t)0, 1.f);
    row_stats_kernel<<<BQ_, 256>>>(QP, qsq, qrn);

    // ---- pairwise ----
    mma_gemm_nt<<<dim3(NC_/128, BQ_/128, 1), 256>>>(
        QP, KP, (const float*)nullptr, GQK, D_, D_, D_, NC_, 0, (size_t)0, 1.f);
    mma_gemm_nt<<<dim3(NC_/128, BQ_/128, H_), 256>>>(
        QH, KH, (const float*)nullptr, S, HD_, D_, D_, NC_, HD_, (size_t)BQ_ * NC_,
        0.08838834764831845f /* 1/sqrt(128) */);

    softmax_stats_kernel<<<dim3(BQ_, H_), 256>>>(S, Mst, Lst);
    final_kernel<<<dim3(NC_/256, BQ_), 256>>>(
        GQK, S, qsq, qrn, ksq, krn, Mst, Lst, fw1, fb1, fw2, fb2, temp, (float*)d_out);
}

// round 10
// speedup vs baseline: 2.9313x; 1.0506x over previous
#include <cuda_runtime.h>
#include <math.h>
#include <stdint.h>

#define D_   1024
#define BQ_  1024
#define NC_  16384
#define H_   8
#define HD_  128

// ---------------- scratch (device globals: allocation-free) ----------------
__device__ float g_buf [NC_ * D_];
__device__ float g_KP  [NC_ * D_];
__device__ float g_KH  [NC_ * D_];
__device__ float g_qbuf[BQ_ * D_];
__device__ float g_QP  [BQ_ * D_];
__device__ float g_QH  [BQ_ * D_];
__device__ float g_GQK [(size_t)BQ_ * NC_];
__device__ float g_S   [(size_t)H_ * BQ_ * NC_];
__device__ float g_Wt  [6 * (size_t)D_ * D_];      // transposed weights
__device__ float g_ksq [NC_], g_krn[NC_];
__device__ float g_qsq [BQ_], g_qrn[BQ_];
__device__ float g_m   [BQ_ * H_], g_l[BQ_ * H_];

// ====================== warp-level MMA helpers (tf32, legacy path) ==========
__device__ __forceinline__ uint32_t s2u(const void* p) {
    uint32_t a;
    asm("{ .reg .u64 t; cvta.to.shared.u64 t, %1; cvt.u32.u64 %0, t; }"
        : "=r"(a) : "l"(p));
    return a;
}
__device__ __forceinline__ void ldsm4(uint32_t* r, uint32_t addr) {
    asm volatile("ldmatrix.sync.aligned.m8n8.x4.shared.b16 {%0,%1,%2,%3}, [%4];"
                 : "=r"(r[0]), "=r"(r[1]), "=r"(r[2]), "=r"(r[3]) : "r"(addr));
}
__device__ __forceinline__ void mma8(float* c, const uint32_t* a, const uint32_t* b) {
    asm volatile(
        "mma.sync.aligned.m16n8k8.row.col.f32.tf32.tf32.f32 "
        "{%0,%1,%2,%3}, {%4,%5,%6,%7}, {%8,%9}, {%0,%1,%2,%3};"
        : "+f"(c[0]), "+f"(c[1]), "+f"(c[2]), "+f"(c[3])
        : "r"(a[0]), "r"(a[1]), "r"(a[2]), "r"(a[3]), "r"(b[0]), "r"(b[1]));
}
#define CP_ASYNC16(dst, src) \
    asm volatile("cp.async.cg.shared.global [%0], [%1], 16;" :: "r"(dst), "l"(src))
#define CP_COMMIT() asm volatile("cp.async.commit_group;" ::: "memory")
#define CP_WAIT(n)  asm volatile("cp.async.wait_group %0;" :: "n"(n) : "memory")

// ============ tf32 NT GEMM: C = scale * A[M,K] @ B[N,K]^T + bias ============
// CTA tile 128x128, K-chunk 16. 8 warps as 2(m) x 4(n), warp tile 64x32.
// cp.async 3-stage pipeline, 48KB static smem (16KB/stage), 2 CTAs/SM.
// Packed smem layout per chunk: tile row R, k-granule g (16B, g=0..3):
//   off(R,g) = (R>>1)*128 + (R&1)*64 + ((g ^ ((R>>1)&3))<<4)
// -> conflict-free for cp.async stores and all 8-lane ldmatrix phases.
// z-dim heads: koff = z*koffz on A and B; C += z*zStrideC.
__global__ __launch_bounds__(256, 2) void mma_gemm_nt(
    const float* __restrict__ A, const float* __restrict__ B,
    const float* __restrict__ bias, float* __restrict__ C,
    int K, int lda, int ldb, int ldc,
    int koffz, size_t zStrideC, float scale)
{
    __shared__ __align__(1024) char smem[49152];   // 3 stages x (A 8KB + B 8KB)

    const int tid  = threadIdx.x;
    const int lane = tid & 31;
    const int wid  = tid >> 5;
    const int wm   = wid & 1;          // 0..1
    const int wn   = wid >> 1;         // 0..3
    const int m0   = wm * 64;
    const int n0   = wn * 32;
    const int bm   = blockIdx.y * 128;
    const int bn   = blockIdx.x * 128;
    const int z    = blockIdx.z;
    const int koff = z * koffz;

    const uint32_t base = s2u(smem);

    // A lane addressing: lanes 0-7 rows+0..7, 8-15 rows+8..15 (tiles a0/a1),
    // lanes 16-31 repeat rows with second k-granule (tiles a2/a3).
    const int  RbA = ((lane >> 3) & 1) * 8 + (lane & 7);
    const uint32_t glA = (uint32_t)((lane >> 4) & 1);
    uint32_t rowOffA[4], keyA[4];
    #pragma unroll
    for (int mf = 0; mf < 4; mf++) {
        int R = m0 + mf * 16 + RbA;
        rowOffA[mf] = (uint32_t)((R >> 1) * 128 + (R & 1) * 64);
        keyA[mf]    = (uint32_t)((R >> 1) & 3);
    }
    // B lane addressing: lanes 0-15 n-rows+0..7 (granules g,g+1 = tiles b0/b1),
    // lanes 16-31 n-rows+8..15.
    const uint32_t glB = (uint32_t)((lane >> 3) & 1);
    uint32_t rowOffB[2], keyB[2];
    #pragma unroll
    for (int p = 0; p < 2; p++) {
        int R = n0 + p * 16 + ((lane >> 4) & 1) * 8 + (lane & 7);
        rowOffB[p] = 8192u + (uint32_t)((R >> 1) * 128 + (R & 1) * 64);
        keyB[p]    = (uint32_t)((R >> 1) & 3);
    }

    const float* Ab = A + (size_t)bm * lda + koff;
    const float* Bb = B + (size_t)bn * ldb + koff;

    float acc[4][4][4];
    #pragma unroll
    for (int i = 0; i < 4; i++)
        #pragma unroll
        for (int j = 0; j < 4; j++)
            #pragma unroll
            for (int k = 0; k < 4; k++) acc[i][j][k] = 0.f;

    const int NIT = K >> 4;             // K16 chunks (>= 8 for all our shapes)

    // loader: 512 float4 per operand per chunk; thread does 2 A + 2 B cp.async
    #define LOAD_CHUNK(k0, stage) do {                                          \
        uint32_t sb_ = base + (uint32_t)(stage) * 16384u;                       \
        _Pragma("unroll")                                                       \
        for (int i_ = 0; i_ < 2; i_++) {                                        \
            int f_ = tid + i_ * 256;                                            \
            int R_ = f_ >> 2, g_ = f_ & 3;                                      \
            uint32_t off_ = (uint32_t)((R_ >> 1) * 128 + (R_ & 1) * 64          \
                          + ((g_ ^ ((R_ >> 1) & 3)) << 4));                     \
            CP_ASYNC16(sb_ + off_,        &Ab[(size_t)R_ * lda + (k0) + g_*4]); \
            CP_ASYNC16(sb_ + 8192u + off_,&Bb[(size_t)R_ * ldb + (k0) + g_*4]); \
        }                                                                       \
    } while (0)

    LOAD_CHUNK(0, 0);  CP_COMMIT();
    LOAD_CHUNK(16, 1); CP_COMMIT();

    for (int it = 0; it < NIT; ++it) {
        if (it + 2 < NIT) {
            LOAD_CHUNK((it + 2) * 16, (it + 2) % 3);
            CP_COMMIT();
            CP_WAIT(2);                 // chunk 'it' resident
        } else {
            CP_WAIT(0);
        }
        __syncthreads();

        const uint32_t sb = base + (uint32_t)(it % 3) * 16384u;
        #pragma unroll
        for (int ks = 0; ks < 2; ks++) {
            uint32_t b[2][4];
            uint32_t GB = (uint32_t)(ks * 2) + glB;
            ldsm4(b[0], sb + rowOffB[0] + ((GB ^ keyB[0]) << 4));
            ldsm4(b[1], sb + rowOffB[1] + ((GB ^ keyB[1]) << 4));
            uint32_t a[4][4];
            uint32_t GA = (uint32_t)(ks * 2) + glA;
            #pragma unroll
            for (int mf = 0; mf < 4; mf++)
                ldsm4(a[mf], sb + rowOffA[mf] + ((GA ^ keyA[mf]) << 4));
            #pragma unroll
            for (int mf = 0; mf < 4; mf++) {
                mma8(acc[mf][0], a[mf], &b[0][0]);
                mma8(acc[mf][1], a[mf], &b[0][2]);
                mma8(acc[mf][2], a[mf], &b[1][0]);
                mma8(acc[mf][3], a[mf], &b[1][2]);
            }
        }
        __syncthreads();   // stage (it%3) reused by chunk it+3's loads
    }

    // epilogue: scale + bias (via __ldg), float2 stores
    float* Cz = C + (size_t)z * zStrideC;
    #pragma unroll
    for (int mf = 0; mf < 4; mf++) {
        int r0 = bm + m0 + mf * 16 + (lane >> 2);
        #pragma unroll
        for (int nf = 0; nf < 4; nf++) {
            int cl = n0 + nf * 8 + (lane & 3) * 2;
            float b0 = bias ? __ldg(&bias[bn + cl])     : 0.f;
            float b1 = bias ? __ldg(&bias[bn + cl + 1]) : 0.f;
            float2 v0, v1;
            v0.x = acc[mf][nf][0] * scale + b0;
            v0.y = acc[mf][nf][1] * scale + b1;
            v1.x = acc[mf][nf][2] * scale + b0;
            v1.y = acc[mf][nf][3] * scale + b1;
            *(float2*)&Cz[(size_t)r0 * ldc + bn + cl]       = v0;
            *(float2*)&Cz[(size_t)(r0 + 8) * ldc + bn + cl] = v1;
        }
    }
    #undef LOAD_CHUNK
}

// ---------------- 1024x1024 transpose (for weights -> NT form) ----------------
__global__ __launch_bounds__(256) void transpose_k(
    const float* __restrict__ in, float* __restrict__ out)
{
    __shared__ float t[32][33];
    int x  = blockIdx.x * 32 + threadIdx.x;
    int y0 = blockIdx.y * 32;
    #pragma unroll
    for (int j = threadIdx.y; j < 32; j += 8)
        t[j][threadIdx.x] = in[(size_t)(y0 + j) * D_ + x];
    __syncthreads();
    int x2 = blockIdx.y * 32 + threadIdx.x;
    int y2 = blockIdx.x * 32;
    #pragma unroll
    for (int j = threadIdx.y; j < 32; j += 8)
        out[(size_t)(y2 + j) * D_ + x2] = t[threadIdx.x][j];
}

// ---------------- LayerNorm + exact GELU, in place ----------------
__global__ __launch_bounds__(256) void ln_gelu_kernel(
    float* __restrict__ X, const float* __restrict__ g, const float* __restrict__ be)
{
    __shared__ float sh[256];
    int row = blockIdx.x;
    float* xr = X + (size_t)row * D_;
    float v[4]; float s = 0.f, s2 = 0.f;
    #pragma unroll
    for (int i = 0; i < 4; i++) {
        int c = threadIdx.x + i * 256;
        v[i] = xr[c]; s += v[i]; s2 += v[i] * v[i];
    }
    sh[threadIdx.x] = s; __syncthreads();
    for (int st = 128; st > 0; st >>= 1) {
        if (threadIdx.x < st) sh[threadIdx.x] += sh[threadIdx.x + st];
        __syncthreads();
    }
    float mean = sh[0] * (1.f / D_); __syncthreads();
    sh[threadIdx.x] = s2; __syncthreads();
    for (int st = 128; st > 0; st >>= 1) {
        if (threadIdx.x < st) sh[threadIdx.x] += sh[threadIdx.x + st];
        __syncthreads();
    }
    float var  = sh[0] * (1.f / D_) - mean * mean;
    float rstd = rsqrtf(var + 1e-5f);
    #pragma unroll
    for (int i = 0; i < 4; i++) {
        int c = threadIdx.x + i * 256;
        float y = (v[i] - mean) * rstd * g[c] + be[c];
        xr[c] = 0.5f * y * (1.f + erff(y * 0.7071067811865475f));
    }
}

// ---------------- per-row sum of squares + reciprocal norm ----------------
__global__ __launch_bounds__(256) void row_stats_kernel(
    const float* __restrict__ X, float* __restrict__ sq, float* __restrict__ rn)
{
    __shared__ float sh[256];
    int row = blockIdx.x;
    const float* xr = X + (size_t)row * D_;
    float s2 = 0.f;
    #pragma unroll
    for (int i = 0; i < 4; i++) { float v = xr[threadIdx.x + i * 256]; s2 += v * v; }
    sh[threadIdx.x] = s2; __syncthreads();
    for (int st = 128; st > 0; st >>= 1) {
        if (threadIdx.x < st) sh[threadIdx.x] += sh[threadIdx.x + st];
        __syncthreads();
    }
    if (threadIdx.x == 0) { sq[row] = sh[0]; rn[row] = rsqrtf(sh[0]); }
}

// ---------------- softmax stats per (b,h): two-pass (max, then sum-exp) --------
__global__ __launch_bounds__(256) void softmax_stats_kernel(
    const float* __restrict__ S, float* __restrict__ Mo, float* __restrict__ Lo)
{
    int b = blockIdx.x, h = blockIdx.y;
    int tid = threadIdx.x;
    const float4* row = (const float4*)(S + ((size_t)h * BQ_ + b) * NC_);
    __shared__ float sm[256], sl[256];

    float m = -1e30f;
    for (int i = tid; i < NC_ / 4; i += 256) {
        float4 v = row[i];
        m = fmaxf(m, fmaxf(fmaxf(v.x, v.y), fmaxf(v.z, v.w)));
    }
    sm[tid] = m; __syncthreads();
    for (int st = 128; st > 0; st >>= 1) {
        if (tid < st) sm[tid] = fmaxf(sm[tid], sm[tid + st]);
        __syncthreads();
    }
    m = sm[0];

    float l = 0.f;
    for (int i = tid; i < NC_ / 4; i += 256) {
        float4 v = row[i];
        l += __expf(v.x - m) + __expf(v.y - m) + __expf(v.z - m) + __expf(v.w - m);
    }
    sl[tid] = l; __syncthreads();
    for (int st = 128; st > 0; st >>= 1) {
        if (tid < st) sl[tid] += sl[tid + st];
        __syncthreads();
    }
    if (tid == 0) { Mo[b * H_ + h] = m; Lo[b * H_ + h] = sl[0]; }
}

// ---------------- final fused: features + fusion MLP + sigmoid ----------------
__global__ __launch_bounds__(256) void final_kernel(
    const float* __restrict__ GQK, const float* __restrict__ S,
    const float* __restrict__ qsq, const float* __restrict__ qrn,
    const float* __restrict__ ksq, const float* __restrict__ krn,
    const float* __restrict__ Mst, const float* __restrict__ Lst,
    const float* __restrict__ fw1, const float* __restrict__ fb1,
    const float* __restrict__ fw2, const float* __restrict__ fb2,
    const float* __restrict__ temp, float* __restrict__ out)
{
    __shared__ float sW1[192], sB1[64], sW2[64];
    __shared__ float sM[8], sIL[8];
    __shared__ float sb2, sET, sQsq, sQrn;
    int tid = threadIdx.x;
    int b = blockIdx.y;
    if (tid < 192) sW1[tid] = fw1[tid];
    if (tid < 64) { sB1[tid] = fb1[tid]; sW2[tid] = fw2[tid]; }
    if (tid < 8)  { sM[tid] = Mst[b * H_ + tid]; sIL[tid] = 1.f / Lst[b * H_ + tid]; }
    if (tid == 0) { sb2 = fb2[0]; sET = expf(temp[0]); sQsq = qsq[b]; sQrn = qrn[b]; }
    __syncthreads();

    int n = blockIdx.x * 256 + tid;
    float g = GQK[(size_t)b * NC_ + n];
    float cosv = g * sQrn * krn[n] * sET;
    float d2 = fmaxf(sQsq + ksq[n] - 2.f * g, 0.f);
    float euc = 1.f / (1.f + sqrtf(d2));
    float lsum = 0.f;
    #pragma unroll
    for (int h = 0; h < 8; h++) {
        float s = S[((size_t)h * BQ_ + b) * NC_ + n];
        lsum += __expf(s - sM[h]) * sIL[h];
    }
    float learned = 0.125f * lsum;

    float logit = sb2;
    #pragma unroll 16
    for (int j = 0; j < 64; j++) {
        float hv = cosv * sW1[j] + euc * sW1[64 + j] + learned * sW1[128 + j] + sB1[j];
        hv = fmaxf(hv, 0.f);
        logit += hv * sW2[j];
    }
    out[(size_t)b * NC_ + n] = 1.f / (1.f + __expf(-logit));
}

// ------------------------------- launcher -------------------------------------
extern "C" void kernel_launch(void* const* d_in, const int* in_sizes, int n_in,
                              void* d_out, int out_size)
{
    const float* qf   = (const float*)d_in[0];
    const float* cf   = (const float*)d_in[1];
    const float* temp = (const float*)d_in[2];
    const float* q_w1 = (const float*)d_in[3];
    const float* q_b1 = (const float*)d_in[4];
    const float* q_g  = (const float*)d_in[5];
    const float* q_be = (const float*)d_in[6];
    const float* q_w2 = (const float*)d_in[7];
    const float* q_b2 = (const float*)d_in[8];
    const float* k_w1 = (const float*)d_in[9];
    const float* k_b1 = (const float*)d_in[10];
    const float* k_g  = (const float*)d_in[11];
    const float* k_be = (const float*)d_in[12];
    const float* k_w2 = (const float*)d_in[13];
    const float* k_b2 = (const float*)d_in[14];
    const float* wq   = (const float*)d_in[15];
    const float* bq   = (const float*)d_in[16];
    const float* wk   = (const float*)d_in[17];
    const float* bk   = (const float*)d_in[18];
    const float* fw1  = (const float*)d_in[19];
    const float* fb1  = (const float*)d_in[20];
    const float* fw2  = (const float*)d_in[21];
    const float* fb2  = (const float*)d_in[22];

    float *buf, *KP, *KH, *qbuf, *QP, *QH, *GQK, *S, *Wt;
    float *ksq, *krn, *qsq, *qrn, *Mst, *Lst;
    cudaGetSymbolAddress((void**)&buf,  g_buf);
    cudaGetSymbolAddress((void**)&KP,   g_KP);
    cudaGetSymbolAddress((void**)&KH,   g_KH);
    cudaGetSymbolAddress((void**)&qbuf, g_qbuf);
    cudaGetSymbolAddress((void**)&QP,   g_QP);
    cudaGetSymbolAddress((void**)&QH,   g_QH);
    cudaGetSymbolAddress((void**)&GQK,  g_GQK);
    cudaGetSymbolAddress((void**)&S,    g_S);
    cudaGetSymbolAddress((void**)&Wt,   g_Wt);
    cudaGetSymbolAddress((void**)&ksq,  g_ksq);
    cudaGetSymbolAddress((void**)&krn,  g_krn);
    cudaGetSymbolAddress((void**)&qsq,  g_qsq);
    cudaGetSymbolAddress((void**)&qrn,  g_qrn);
    cudaGetSymbolAddress((void**)&Mst,  g_m);
    cudaGetSymbolAddress((void**)&Lst,  g_l);

    static const size_t WSZ = (size_t)D_ * D_;
    float* Wt_kw1 = Wt + 0 * WSZ;
    float* Wt_kw2 = Wt + 1 * WSZ;
    float* Wt_wk  = Wt + 2 * WSZ;
    float* Wt_qw1 = Wt + 3 * WSZ;
    float* Wt_qw2 = Wt + 4 * WSZ;
    float* Wt_wq  = Wt + 5 * WSZ;

    // ---- weight transposes (W[K,N] -> Wt[N,K]) ----
    dim3 tb(32, 8), tg(32, 32);
    transpose_k<<<tg, tb>>>(k_w1, Wt_kw1);
    transpose_k<<<tg, tb>>>(k_w2, Wt_kw2);
    transpose_k<<<tg, tb>>>(wk,   Wt_wk);
    transpose_k<<<tg, tb>>>(q_w1, Wt_qw1);
    transpose_k<<<tg, tb>>>(q_w2, Wt_qw2);
    transpose_k<<<tg, tb>>>(wq,   Wt_wq);

    // ---- key path ----
    mma_gemm_nt<<<dim3(D_/128, NC_/128, 1), 256>>>(
        cf, Wt_kw1, k_b1, buf, D_, D_, D_, D_, 0, (size_t)0, 1.f);
    ln_gelu_kernel<<<NC_, 256>>>(buf, k_g, k_be);
    mma_gemm_nt<<<dim3(D_/128, NC_/128, 1), 256>>>(
        buf, Wt_kw2, k_b2, KP, D_, D_, D_, D_, 0, (size_t)0, 1.f);
    mma_gemm_nt<<<dim3(D_/128, NC_/128, 1), 256>>>(
        KP, Wt_wk, bk, KH, D_, D_, D_, D_, 0, (size_t)0, 1.f);
    row_stats_kernel<<<NC_, 256>>>(KP, ksq, krn);

    // ---- query path ----
    mma_gemm_nt<<<dim3(D_/128, BQ_/128, 1), 256>>>(
        qf, Wt_qw1, q_b1, qbuf, D_, D_, D_, D_, 0, (size_t)0, 1.f);
    ln_gelu_kernel<<<BQ_, 256>>>(qbuf, q_g, q_be);
    mma_gemm_nt<<<dim3(D_/128, BQ_/128, 1), 256>>>(
        qbuf, Wt_qw2, q_b2, QP, D_, D_, D_, D_, 0, (size_t)0, 1.f);
    mma_gemm_nt<<<dim3(D_/128, BQ_/128, 1), 256>>>(
        QP, Wt_wq, bq, QH, D_, D_, D_, D_, 0, (size_t)0, 1.f);
    row_stats_kernel<<<BQ_, 256>>>(QP, qsq, qrn);

    // ---- pairwise ----
    mma_gemm_nt<<<dim3(NC_/128, BQ_/128, 1), 256>>>(
        QP, KP, (const float*)nullptr, GQK, D_, D_, D_, NC_, 0, (size_t)0, 1.f);
    mma_gemm_nt<<<dim3(NC_/128, BQ_/128, H_), 256>>>(
        QH, KH, (const float*)nullptr, S, HD_, D_, D_, NC_, HD_, (size_t)BQ_ * NC_,
        0.08838834764831845f /* 1/sqrt(128) */);

    softmax_stats_kernel<<<dim3(BQ_, H_), 256>>>(S, Mst, Lst);
    final_kernel<<<dim3(NC_/256, BQ_), 256>>>(
        GQK, S, qsq, qrn, ksq, krn, Mst, Lst, fw1, fb1, fw2, fb2, temp, (float*)d_out);
}

// round 11
// speedup vs baseline: 2.9336x; 1.0008x over previous
#include <cuda_runtime.h>
#include <math.h>
#include <stdint.h>

#define D_   1024
#define BQ_  1024
#define NC_  16384
#define H_   8
#define HD_  128

// ---------------- scratch (device globals: allocation-free) ----------------
__device__ float g_buf [NC_ * D_];
__device__ float g_KP  [NC_ * D_];
__device__ float g_KH  [NC_ * D_];
__device__ float g_qbuf[BQ_ * D_];
__device__ float g_QP  [BQ_ * D_];
__device__ float g_QH  [BQ_ * D_];
__device__ float g_GQK [(size_t)BQ_ * NC_];
__device__ float g_S   [(size_t)H_ * BQ_ * NC_];
__device__ float g_Wt  [6 * (size_t)D_ * D_];      // transposed weights
__device__ float g_ksq [NC_], g_krn[NC_];
__device__ float g_qsq [BQ_], g_qrn[BQ_];
__device__ float g_m   [BQ_ * H_], g_l[BQ_ * H_];

// ====================== warp-level MMA helpers (tf32, legacy path) ==========
__device__ __forceinline__ uint32_t s2u(const void* p) {
    uint32_t a;
    asm("{ .reg .u64 t; cvta.to.shared.u64 t, %1; cvt.u32.u64 %0, t; }"
        : "=r"(a) : "l"(p));
    return a;
}
__device__ __forceinline__ void ldsm4(uint32_t* r, uint32_t addr) {
    asm volatile("ldmatrix.sync.aligned.m8n8.x4.shared.b16 {%0,%1,%2,%3}, [%4];"
                 : "=r"(r[0]), "=r"(r[1]), "=r"(r[2]), "=r"(r[3]) : "r"(addr));
}
__device__ __forceinline__ void mma8(float* c, const uint32_t* a, const uint32_t* b) {
    asm volatile(
        "mma.sync.aligned.m16n8k8.row.col.f32.tf32.tf32.f32 "
        "{%0,%1,%2,%3}, {%4,%5,%6,%7}, {%8,%9}, {%0,%1,%2,%3};"
        : "+f"(c[0]), "+f"(c[1]), "+f"(c[2]), "+f"(c[3])
        : "r"(a[0]), "r"(a[1]), "r"(a[2]), "r"(a[3]), "r"(b[0]), "r"(b[1]));
}
#define CP_ASYNC16(dst, src) \
    asm volatile("cp.async.cg.shared.global [%0], [%1], 16;" :: "r"(dst), "l"(src))
#define CP_COMMIT() asm volatile("cp.async.commit_group;" ::: "memory")
#define CP_WAIT(n)  asm volatile("cp.async.wait_group %0;" :: "n"(n) : "memory")

// ============ tf32 NT GEMM: C = scale * A[M,K] @ B[N,K]^T + bias ============
// CTA tile 128x128, K-chunk 16. 8 warps as 2(m) x 4(n), warp tile 64x32.
// cp.async 3-stage pipeline, 48KB static smem (16KB/stage), 2 CTAs/SM.
// Packed smem layout per chunk: tile row R, k-granule g (16B, g=0..3):
//   off(R,g) = (R>>1)*128 + (R&1)*64 + ((g ^ ((R>>1)&3))<<4)
// -> conflict-free for cp.async stores and all 8-lane ldmatrix phases.
// z-dim heads: koff = z*koffz on A and B; C += z*zStrideC.
__global__ __launch_bounds__(256, 2) void mma_gemm_nt(
    const float* __restrict__ A, const float* __restrict__ B,
    const float* __restrict__ bias, float* __restrict__ C,
    int K, int lda, int ldb, int ldc,
    int koffz, size_t zStrideC, float scale)
{
    __shared__ __align__(1024) char smem[49152];   // 3 stages x (A 8KB + B 8KB)

    const int tid  = threadIdx.x;
    const int lane = tid & 31;
    const int wid  = tid >> 5;
    const int wm   = wid & 1;          // 0..1
    const int wn   = wid >> 1;         // 0..3
    const int m0   = wm * 64;
    const int n0   = wn * 32;
    const int bm   = blockIdx.y * 128;
    const int bn   = blockIdx.x * 128;
    const int z    = blockIdx.z;
    const int koff = z * koffz;

    const uint32_t base = s2u(smem);

    // A lane addressing: lanes 0-7 rows+0..7, 8-15 rows+8..15 (tiles a0/a1),
    // lanes 16-31 repeat rows with second k-granule (tiles a2/a3).
    const int  RbA = ((lane >> 3) & 1) * 8 + (lane & 7);
    const uint32_t glA = (uint32_t)((lane >> 4) & 1);
    uint32_t rowOffA[4], keyA[4];
    #pragma unroll
    for (int mf = 0; mf < 4; mf++) {
        int R = m0 + mf * 16 + RbA;
        rowOffA[mf] = (uint32_t)((R >> 1) * 128 + (R & 1) * 64);
        keyA[mf]    = (uint32_t)((R >> 1) & 3);
    }
    // B lane addressing: lanes 0-15 n-rows+0..7 (granules g,g+1 = tiles b0/b1),
    // lanes 16-31 n-rows+8..15.
    const uint32_t glB = (uint32_t)((lane >> 3) & 1);
    uint32_t rowOffB[2], keyB[2];
    #pragma unroll
    for (int p = 0; p < 2; p++) {
        int R = n0 + p * 16 + ((lane >> 4) & 1) * 8 + (lane & 7);
        rowOffB[p] = 8192u + (uint32_t)((R >> 1) * 128 + (R & 1) * 64);
        keyB[p]    = (uint32_t)((R >> 1) & 3);
    }

    const float* Ab = A + (size_t)bm * lda + koff;
    const float* Bb = B + (size_t)bn * ldb + koff;

    float acc[4][4][4];
    #pragma unroll
    for (int i = 0; i < 4; i++)
        #pragma unroll
        for (int j = 0; j < 4; j++)
            #pragma unroll
            for (int k = 0; k < 4; k++) acc[i][j][k] = 0.f;

    const int NIT = K >> 4;             // K16 chunks (>= 8 for all our shapes)

    // loader: 512 float4 per operand per chunk; thread does 2 A + 2 B cp.async
    #define LOAD_CHUNK(k0, stage) do {                                          \
        uint32_t sb_ = base + (uint32_t)(stage) * 16384u;                       \
        _Pragma("unroll")                                                       \
        for (int i_ = 0; i_ < 2; i_++) {                                        \
            int f_ = tid + i_ * 256;                                            \
            int R_ = f_ >> 2, g_ = f_ & 3;                                      \
            uint32_t off_ = (uint32_t)((R_ >> 1) * 128 + (R_ & 1) * 64          \
                          + ((g_ ^ ((R_ >> 1) & 3)) << 4));                     \
            CP_ASYNC16(sb_ + off_,        &Ab[(size_t)R_ * lda + (k0) + g_*4]); \
            CP_ASYNC16(sb_ + 8192u + off_,&Bb[(size_t)R_ * ldb + (k0) + g_*4]); \
        }                                                                       \
    } while (0)

    LOAD_CHUNK(0, 0);  CP_COMMIT();
    LOAD_CHUNK(16, 1); CP_COMMIT();

    for (int it = 0; it < NIT; ++it) {
        if (it + 2 < NIT) {
            LOAD_CHUNK((it + 2) * 16, (it + 2) % 3);
            CP_COMMIT();
            CP_WAIT(2);                 // chunk 'it' resident
        } else {
            CP_WAIT(0);
        }
        __syncthreads();

        const uint32_t sb = base + (uint32_t)(it % 3) * 16384u;
        #pragma unroll
        for (int ks = 0; ks < 2; ks++) {
            uint32_t b[2][4];
            uint32_t GB = (uint32_t)(ks * 2) + glB;
            ldsm4(b[0], sb + rowOffB[0] + ((GB ^ keyB[0]) << 4));
            ldsm4(b[1], sb + rowOffB[1] + ((GB ^ keyB[1]) << 4));
            uint32_t a[4][4];
            uint32_t GA = (uint32_t)(ks * 2) + glA;
            #pragma unroll
            for (int mf = 0; mf < 4; mf++)
                ldsm4(a[mf], sb + rowOffA[mf] + ((GA ^ keyA[mf]) << 4));
            #pragma unroll
            for (int mf = 0; mf < 4; mf++) {
                mma8(acc[mf][0], a[mf], &b[0][0]);
                mma8(acc[mf][1], a[mf], &b[0][2]);
                mma8(acc[mf][2], a[mf], &b[1][0]);
                mma8(acc[mf][3], a[mf], &b[1][2]);
            }
        }
        __syncthreads();   // stage (it%3) reused by chunk it+3's loads
    }

    // epilogue: scale + bias (via __ldg), float2 stores
    float* Cz = C + (size_t)z * zStrideC;
    #pragma unroll
    for (int mf = 0; mf < 4; mf++) {
        int r0 = bm + m0 + mf * 16 + (lane >> 2);
        #pragma unroll
        for (int nf = 0; nf < 4; nf++) {
            int cl = n0 + nf * 8 + (lane & 3) * 2;
            float b0 = bias ? __ldg(&bias[bn + cl])     : 0.f;
            float b1 = bias ? __ldg(&bias[bn + cl + 1]) : 0.f;
            float2 v0, v1;
            v0.x = acc[mf][nf][0] * scale + b0;
            v0.y = acc[mf][nf][1] * scale + b1;
            v1.x = acc[mf][nf][2] * scale + b0;
            v1.y = acc[mf][nf][3] * scale + b1;
            *(float2*)&Cz[(size_t)r0 * ldc + bn + cl]       = v0;
            *(float2*)&Cz[(size_t)(r0 + 8) * ldc + bn + cl] = v1;
        }
    }
    #undef LOAD_CHUNK
}

// ---------------- 1024x1024 transpose (for weights -> NT form) ----------------
__global__ __launch_bounds__(256) void transpose_k(
    const float* __restrict__ in, float* __restrict__ out)
{
    __shared__ float t[32][33];
    int x  = blockIdx.x * 32 + threadIdx.x;
    int y0 = blockIdx.y * 32;
    #pragma unroll
    for (int j = threadIdx.y; j < 32; j += 8)
        t[j][threadIdx.x] = in[(size_t)(y0 + j) * D_ + x];
    __syncthreads();
    int x2 = blockIdx.y * 32 + threadIdx.x;
    int y2 = blockIdx.x * 32;
    #pragma unroll
    for (int j = threadIdx.y; j < 32; j += 8)
        out[(size_t)(y2 + j) * D_ + x2] = t[threadIdx.x][j];
}

// ---------------- LayerNorm + exact GELU, in place ----------------
__global__ __launch_bounds__(256) void ln_gelu_kernel(
    float* __restrict__ X, const float* __restrict__ g, const float* __restrict__ be)
{
    __shared__ float sh[256];
    int row = blockIdx.x;
    float* xr = X + (size_t)row * D_;
    float v[4]; float s = 0.f, s2 = 0.f;
    #pragma unroll
    for (int i = 0; i < 4; i++) {
        int c = threadIdx.x + i * 256;
        v[i] = xr[c]; s += v[i]; s2 += v[i] * v[i];
    }
    sh[threadIdx.x] = s; __syncthreads();
    for (int st = 128; st > 0; st >>= 1) {
        if (threadIdx.x < st) sh[threadIdx.x] += sh[threadIdx.x + st];
        __syncthreads();
    }
    float mean = sh[0] * (1.f / D_); __syncthreads();
    sh[threadIdx.x] = s2; __syncthreads();
    for (int st = 128; st > 0; st >>= 1) {
        if (threadIdx.x < st) sh[threadIdx.x] += sh[threadIdx.x + st];
        __syncthreads();
    }
    float var  = sh[0] * (1.f / D_) - mean * mean;
    float rstd = rsqrtf(var + 1e-5f);
    #pragma unroll
    for (int i = 0; i < 4; i++) {
        int c = threadIdx.x + i * 256;
        float y = (v[i] - mean) * rstd * g[c] + be[c];
        xr[c] = 0.5f * y * (1.f + erff(y * 0.7071067811865475f));
    }
}

// ---------------- per-row sum of squares + reciprocal norm ----------------
__global__ __launch_bounds__(256) void row_stats_kernel(
    const float* __restrict__ X, float* __restrict__ sq, float* __restrict__ rn)
{
    __shared__ float sh[256];
    int row = blockIdx.x;
    const float* xr = X + (size_t)row * D_;
    float s2 = 0.f;
    #pragma unroll
    for (int i = 0; i < 4; i++) { float v = xr[threadIdx.x + i * 256]; s2 += v * v; }
    sh[threadIdx.x] = s2; __syncthreads();
    for (int st = 128; st > 0; st >>= 1) {
        if (threadIdx.x < st) sh[threadIdx.x] += sh[threadIdx.x + st];
        __syncthreads();
    }
    if (threadIdx.x == 0) { sq[row] = sh[0]; rn[row] = rsqrtf(sh[0]); }
}

// ---------------- softmax stats per (b,h): two-pass (max, then sum-exp) --------
__global__ __launch_bounds__(256) void softmax_stats_kernel(
    const float* __restrict__ S, float* __restrict__ Mo, float* __restrict__ Lo)
{
    int b = blockIdx.x, h = blockIdx.y;
    int tid = threadIdx.x;
    const float4* row = (const float4*)(S + ((size_t)h * BQ_ + b) * NC_);
    __shared__ float sm[256], sl[256];

    float m = -1e30f;
    for (int i = tid; i < NC_ / 4; i += 256) {
        float4 v = row[i];
        m = fmaxf(m, fmaxf(fmaxf(v.x, v.y), fmaxf(v.z, v.w)));
    }
    sm[tid] = m; __syncthreads();
    for (int st = 128; st > 0; st >>= 1) {
        if (tid < st) sm[tid] = fmaxf(sm[tid], sm[tid + st]);
        __syncthreads();
    }
    m = sm[0];

    float l = 0.f;
    for (int i = tid; i < NC_ / 4; i += 256) {
        float4 v = row[i];
        l += __expf(v.x - m) + __expf(v.y - m) + __expf(v.z - m) + __expf(v.w - m);
    }
    sl[tid] = l; __syncthreads();
    for (int st = 128; st > 0; st >>= 1) {
        if (tid < st) sl[tid] += sl[tid + st];
        __syncthreads();
    }
    if (tid == 0) { Mo[b * H_ + h] = m; Lo[b * H_ + h] = sl[0]; }
}

// ---------------- final fused: features + fusion MLP + sigmoid ----------------
__global__ __launch_bounds__(256) void final_kernel(
    const float* __restrict__ GQK, const float* __restrict__ S,
    const float* __restrict__ qsq, const float* __restrict__ qrn,
    const float* __restrict__ ksq, const float* __restrict__ krn,
    const float* __restrict__ Mst, const float* __restrict__ Lst,
    const float* __restrict__ fw1, const float* __restrict__ fb1,
    const float* __restrict__ fw2, const float* __restrict__ fb2,
    const float* __restrict__ temp, float* __restrict__ out)
{
    __shared__ float sW1[192], sB1[64], sW2[64];
    __shared__ float sM[8], sIL[8];
    __shared__ float sb2, sET, sQsq, sQrn;
    int tid = threadIdx.x;
    int b = blockIdx.y;
    if (tid < 192) sW1[tid] = fw1[tid];
    if (tid < 64) { sB1[tid] = fb1[tid]; sW2[tid] = fw2[tid]; }
    if (tid < 8)  { sM[tid] = Mst[b * H_ + tid]; sIL[tid] = 1.f / Lst[b * H_ + tid]; }
    if (tid == 0) { sb2 = fb2[0]; sET = expf(temp[0]); sQsq = qsq[b]; sQrn = qrn[b]; }
    __syncthreads();

    int n = blockIdx.x * 256 + tid;
    float g = GQK[(size_t)b * NC_ + n];
    float cosv = g * sQrn * krn[n] * sET;
    float d2 = fmaxf(sQsq + ksq[n] - 2.f * g, 0.f);
    float euc = 1.f / (1.f + sqrtf(d2));
    float lsum = 0.f;
    #pragma unroll
    for (int h = 0; h < 8; h++) {
        float s = S[((size_t)h * BQ_ + b) * NC_ + n];
        lsum += __expf(s - sM[h]) * sIL[h];
    }
    float learned = 0.125f * lsum;

    float logit = sb2;
    #pragma unroll 16
    for (int j = 0; j < 64; j++) {
        float hv = cosv * sW1[j] + euc * sW1[64 + j] + learned * sW1[128 + j] + sB1[j];
        hv = fmaxf(hv, 0.f);
        logit += hv * sW2[j];
    }
    out[(size_t)b * NC_ + n] = 1.f / (1.f + __expf(-logit));
}

// ------------------------------- launcher -------------------------------------
extern "C" void kernel_launch(void* const* d_in, const int* in_sizes, int n_in,
                              void* d_out, int out_size)
{
    const float* qf   = (const float*)d_in[0];
    const float* cf   = (const float*)d_in[1];
    const float* temp = (const float*)d_in[2];
    const float* q_w1 = (const float*)d_in[3];
    const float* q_b1 = (const float*)d_in[4];
    const float* q_g  = (const float*)d_in[5];
    const float* q_be = (const float*)d_in[6];
    const float* q_w2 = (const float*)d_in[7];
    const float* q_b2 = (const float*)d_in[8];
    const float* k_w1 = (const float*)d_in[9];
    const float* k_b1 = (const float*)d_in[10];
    const float* k_g  = (const float*)d_in[11];
    const float* k_be = (const float*)d_in[12];
    const float* k_w2 = (const float*)d_in[13];
    const float* k_b2 = (const float*)d_in[14];
    const float* wq   = (const float*)d_in[15];
    const float* bq   = (const float*)d_in[16];
    const float* wk   = (const float*)d_in[17];
    const float* bk   = (const float*)d_in[18];
    const float* fw1  = (const float*)d_in[19];
    const float* fb1  = (const float*)d_in[20];
    const float* fw2  = (const float*)d_in[21];
    const float* fb2  = (const float*)d_in[22];

    float *buf, *KP, *KH, *qbuf, *QP, *QH, *GQK, *S, *Wt;
    float *ksq, *krn, *qsq, *qrn, *Mst, *Lst;
    cudaGetSymbolAddress((void**)&buf,  g_buf);
    cudaGetSymbolAddress((void**)&KP,   g_KP);
    cudaGetSymbolAddress((void**)&KH,   g_KH);
    cudaGetSymbolAddress((void**)&qbuf, g_qbuf);
    cudaGetSymbolAddress((void**)&QP,   g_QP);
    cudaGetSymbolAddress((void**)&QH,   g_QH);
    cudaGetSymbolAddress((void**)&GQK,  g_GQK);
    cudaGetSymbolAddress((void**)&S,    g_S);
    cudaGetSymbolAddress((void**)&Wt,   g_Wt);
    cudaGetSymbolAddress((void**)&ksq,  g_ksq);
    cudaGetSymbolAddress((void**)&krn,  g_krn);
    cudaGetSymbolAddress((void**)&qsq,  g_qsq);
    cudaGetSymbolAddress((void**)&qrn,  g_qrn);
    cudaGetSymbolAddress((void**)&Mst,  g_m);
    cudaGetSymbolAddress((void**)&Lst,  g_l);

    static const size_t WSZ = (size_t)D_ * D_;
    float* Wt_kw1 = Wt + 0 * WSZ;
    float* Wt_kw2 = Wt + 1 * WSZ;
    float* Wt_wk  = Wt + 2 * WSZ;
    float* Wt_qw1 = Wt + 3 * WSZ;
    float* Wt_qw2 = Wt + 4 * WSZ;
    float* Wt_wq  = Wt + 5 * WSZ;

    // ---- weight transposes (W[K,N] -> Wt[N,K]) ----
    dim3 tb(32, 8), tg(32, 32);
    transpose_k<<<tg, tb>>>(k_w1, Wt_kw1);
    transpose_k<<<tg, tb>>>(k_w2, Wt_kw2);
    transpose_k<<<tg, tb>>>(wk,   Wt_wk);
    transpose_k<<<tg, tb>>>(q_w1, Wt_qw1);
    transpose_k<<<tg, tb>>>(q_w2, Wt_qw2);
    transpose_k<<<tg, tb>>>(wq,   Wt_wq);

    // ---- key path ----
    mma_gemm_nt<<<dim3(D_/128, NC_/128, 1), 256>>>(
        cf, Wt_kw1, k_b1, buf, D_, D_, D_, D_, 0, (size_t)0, 1.f);
    ln_gelu_kernel<<<NC_, 256>>>(buf, k_g, k_be);
    mma_gemm_nt<<<dim3(D_/128, NC_/128, 1), 256>>>(
        buf, Wt_kw2, k_b2, KP, D_, D_, D_, D_, 0, (size_t)0, 1.f);
    mma_gemm_nt<<<dim3(D_/128, NC_/128, 1), 256>>>(
        KP, Wt_wk, bk, KH, D_, D_, D_, D_, 0, (size_t)0, 1.f);
    row_stats_kernel<<<NC_, 256>>>(KP, ksq, krn);

    // ---- query path ----
    mma_gemm_nt<<<dim3(D_/128, BQ_/128, 1), 256>>>(
        qf, Wt_qw1, q_b1, qbuf, D_, D_, D_, D_, 0, (size_t)0, 1.f);
    ln_gelu_kernel<<<BQ_, 256>>>(qbuf, q_g, q_be);
    mma_gemm_nt<<<dim3(D_/128, BQ_/128, 1), 256>>>(
        qbuf, Wt_qw2, q_b2, QP, D_, D_, D_, D_, 0, (size_t)0, 1.f);
    mma_gemm_nt<<<dim3(D_/128, BQ_/128, 1), 256>>>(
        QP, Wt_wq, bq, QH, D_, D_, D_, D_, 0, (size_t)0, 1.f);
    row_stats_kernel<<<BQ_, 256>>>(QP, qsq, qrn);

    // ---- pairwise ----
    mma_gemm_nt<<<dim3(NC_/128, BQ_/128, 1), 256>>>(
        QP, KP, (const float*)nullptr, GQK, D_, D_, D_, NC_, 0, (size_t)0, 1.f);
    mma_gemm_nt<<<dim3(NC_/128, BQ_/128, H_), 256>>>(
        QH, KH, (const float*)nullptr, S, HD_, D_, D_, NC_, HD_, (size_t)BQ_ * NC_,
        0.08838834764831845f /* 1/sqrt(128) */);

    softmax_stats_kernel<<<dim3(BQ_, H_), 256>>>(S, Mst, Lst);
    final_kernel<<<dim3(NC_/256, BQ_), 256>>>(
        GQK, S, qsq, qrn, ksq, krn, Mst, Lst, fw1, fb1, fw2, fb2, temp, (float*)d_out);
}

// round 12
// speedup vs baseline: 2.9394x; 1.0020x over previous
#include <cuda_runtime.h>
#include <math.h>
#include <stdint.h>

#define D_   1024
#define BQ_  1024
#define NC_  16384
#define H_   8
#define HD_  128

// ---------------- scratch (device globals: allocation-free) ----------------
__device__ float g_buf [NC_ * D_];
__device__ float g_KP  [NC_ * D_];
__device__ float g_KH  [NC_ * D_];
__device__ float g_qbuf[BQ_ * D_];
__device__ float g_QP  [BQ_ * D_];
__device__ float g_QH  [BQ_ * D_];
__device__ float g_GQK [(size_t)BQ_ * NC_];
__device__ float g_S   [(size_t)H_ * BQ_ * NC_];
__device__ float g_Wt  [6 * (size_t)D_ * D_];      // transposed weights
__device__ float g_ksq [NC_], g_krn[NC_];
__device__ float g_qsq [BQ_], g_qrn[BQ_];
__device__ float g_m   [BQ_ * H_], g_l[BQ_ * H_];

// ====================== warp-level MMA helpers (tf32, legacy path) ==========
__device__ __forceinline__ uint32_t s2u(const void* p) {
    uint32_t a;
    asm("{ .reg .u64 t; cvta.to.shared.u64 t, %1; cvt.u32.u64 %0, t; }"
        : "=r"(a) : "l"(p));
    return a;
}
__device__ __forceinline__ void ldsm4(uint32_t* r, uint32_t addr) {
    asm volatile("ldmatrix.sync.aligned.m8n8.x4.shared.b16 {%0,%1,%2,%3}, [%4];"
                 : "=r"(r[0]), "=r"(r[1]), "=r"(r[2]), "=r"(r[3]) : "r"(addr));
}
__device__ __forceinline__ void mma8(float* c, const uint32_t* a, const uint32_t* b) {
    asm volatile(
        "mma.sync.aligned.m16n8k8.row.col.f32.tf32.tf32.f32 "
        "{%0,%1,%2,%3}, {%4,%5,%6,%7}, {%8,%9}, {%0,%1,%2,%3};"
        : "+f"(c[0]), "+f"(c[1]), "+f"(c[2]), "+f"(c[3])
        : "r"(a[0]), "r"(a[1]), "r"(a[2]), "r"(a[3]), "r"(b[0]), "r"(b[1]));
}
#define CP_ASYNC16(dst, src) \
    asm volatile("cp.async.cg.shared.global [%0], [%1], 16;" :: "r"(dst), "l"(src))
#define CP_COMMIT() asm volatile("cp.async.commit_group;" ::: "memory")
#define CP_WAIT(n)  asm volatile("cp.async.wait_group %0;" :: "n"(n) : "memory")

// ============ tf32 NT GEMM: C = scale * A[M,K] @ B[N,K]^T + bias ============
// CTA tile 128x128, K-chunk 16. 8 warps as 2(m) x 4(n), warp tile 64x32.
// cp.async 3-stage pipeline, 48KB static smem (16KB/stage), 2 CTAs/SM.
// Packed smem layout per chunk: tile row R, k-granule g (16B, g=0..3):
//   off(R,g) = (R>>1)*128 + (R&1)*64 + ((g ^ ((R>>1)&3))<<4)
// -> conflict-free for cp.async stores and all 8-lane ldmatrix phases.
// z-dim heads: koff = z*koffz on A and B; C += z*zStrideC.
__global__ __launch_bounds__(256, 2) void mma_gemm_nt(
    const float* __restrict__ A, const float* __restrict__ B,
    const float* __restrict__ bias, float* __restrict__ C,
    int K, int lda, int ldb, int ldc,
    int koffz, size_t zStrideC, float scale)
{
    __shared__ __align__(1024) char smem[49152];   // 3 stages x (A 8KB + B 8KB)

    const int tid  = threadIdx.x;
    const int lane = tid & 31;
    const int wid  = tid >> 5;
    const int wm   = wid & 1;          // 0..1
    const int wn   = wid >> 1;         // 0..3
    const int m0   = wm * 64;
    const int n0   = wn * 32;
    const int bm   = blockIdx.y * 128;
    const int bn   = blockIdx.x * 128;
    const int z    = blockIdx.z;
    const int koff = z * koffz;

    const uint32_t base = s2u(smem);

    // A lane addressing: lanes 0-7 rows+0..7, 8-15 rows+8..15 (tiles a0/a1),
    // lanes 16-31 repeat rows with second k-granule (tiles a2/a3).
    const int  RbA = ((lane >> 3) & 1) * 8 + (lane & 7);
    const uint32_t glA = (uint32_t)((lane >> 4) & 1);
    uint32_t rowOffA[4], keyA[4];
    #pragma unroll
    for (int mf = 0; mf < 4; mf++) {
        int R = m0 + mf * 16 + RbA;
        rowOffA[mf] = (uint32_t)((R >> 1) * 128 + (R & 1) * 64);
        keyA[mf]    = (uint32_t)((R >> 1) & 3);
    }
    // B lane addressing: lanes 0-15 n-rows+0..7 (granules g,g+1 = tiles b0/b1),
    // lanes 16-31 n-rows+8..15.
    const uint32_t glB = (uint32_t)((lane >> 3) & 1);
    uint32_t rowOffB[2], keyB[2];
    #pragma unroll
    for (int p = 0; p < 2; p++) {
        int R = n0 + p * 16 + ((lane >> 4) & 1) * 8 + (lane & 7);
        rowOffB[p] = 8192u + (uint32_t)((R >> 1) * 128 + (R & 1) * 64);
        keyB[p]    = (uint32_t)((R >> 1) & 3);
    }

    const float* Ab = A + (size_t)bm * lda + koff;
    const float* Bb = B + (size_t)bn * ldb + koff;

    float acc[4][4][4];
    #pragma unroll
    for (int i = 0; i < 4; i++)
        #pragma unroll
        for (int j = 0; j < 4; j++)
            #pragma unroll
            for (int k = 0; k < 4; k++) acc[i][j][k] = 0.f;

    const int NIT = K >> 4;             // K16 chunks (>= 8 for all our shapes)

    // loader: 512 float4 per operand per chunk; thread does 2 A + 2 B cp.async
    #define LOAD_CHUNK(k0, stage) do {                                          \
        uint32_t sb_ = base + (uint32_t)(stage) * 16384u;                       \
        _Pragma("unroll")                                                       \
        for (int i_ = 0; i_ < 2; i_++) {                                        \
            int f_ = tid + i_ * 256;                                            \
            int R_ = f_ >> 2, g_ = f_ & 3;                                      \
            uint32_t off_ = (uint32_t)((R_ >> 1) * 128 + (R_ & 1) * 64          \
                          + ((g_ ^ ((R_ >> 1) & 3)) << 4));                     \
            CP_ASYNC16(sb_ + off_,        &Ab[(size_t)R_ * lda + (k0) + g_*4]); \
            CP_ASYNC16(sb_ + 8192u + off_,&Bb[(size_t)R_ * ldb + (k0) + g_*4]); \
        }                                                                       \
    } while (0)

    LOAD_CHUNK(0, 0);  CP_COMMIT();
    LOAD_CHUNK(16, 1); CP_COMMIT();

    for (int it = 0; it < NIT; ++it) {
        if (it + 2 < NIT) {
            LOAD_CHUNK((it + 2) * 16, (it + 2) % 3);
            CP_COMMIT();
            CP_WAIT(2);                 // chunk 'it' resident
        } else {
            CP_WAIT(0);
        }
        __syncthreads();

        const uint32_t sb = base + (uint32_t)(it % 3) * 16384u;
        #pragma unroll
        for (int ks = 0; ks < 2; ks++) {
            uint32_t b[2][4];
            uint32_t GB = (uint32_t)(ks * 2) + glB;
            ldsm4(b[0], sb + rowOffB[0] + ((GB ^ keyB[0]) << 4));
            ldsm4(b[1], sb + rowOffB[1] + ((GB ^ keyB[1]) << 4));
            uint32_t a[4][4];
            uint32_t GA = (uint32_t)(ks * 2) + glA;
            #pragma unroll
            for (int mf = 0; mf < 4; mf++)
                ldsm4(a[mf], sb + rowOffA[mf] + ((GA ^ keyA[mf]) << 4));
            #pragma unroll
            for (int mf = 0; mf < 4; mf++) {
                mma8(acc[mf][0], a[mf], &b[0][0]);
                mma8(acc[mf][1], a[mf], &b[0][2]);
                mma8(acc[mf][2], a[mf], &b[1][0]);
                mma8(acc[mf][3], a[mf], &b[1][2]);
            }
        }
        __syncthreads();   // stage (it%3) reused by chunk it+3's loads
    }

    // epilogue: scale + bias (via __ldg), float2 stores
    float* Cz = C + (size_t)z * zStrideC;
    #pragma unroll
    for (int mf = 0; mf < 4; mf++) {
        int r0 = bm + m0 + mf * 16 + (lane >> 2);
        #pragma unroll
        for (int nf = 0; nf < 4; nf++) {
            int cl = n0 + nf * 8 + (lane & 3) * 2;
            float b0 = bias ? __ldg(&bias[bn + cl])     : 0.f;
            float b1 = bias ? __ldg(&bias[bn + cl + 1]) : 0.f;
            float2 v0, v1;
            v0.x = acc[mf][nf][0] * scale + b0;
            v0.y = acc[mf][nf][1] * scale + b1;
            v1.x = acc[mf][nf][2] * scale + b0;
            v1.y = acc[mf][nf][3] * scale + b1;
            *(float2*)&Cz[(size_t)r0 * ldc + bn + cl]       = v0;
            *(float2*)&Cz[(size_t)(r0 + 8) * ldc + bn + cl] = v1;
        }
    }
    #undef LOAD_CHUNK
}

// ---------------- 1024x1024 transpose (for weights -> NT form) ----------------
__global__ __launch_bounds__(256) void transpose_k(
    const float* __restrict__ in, float* __restrict__ out)
{
    __shared__ float t[32][33];
    int x  = blockIdx.x * 32 + threadIdx.x;
    int y0 = blockIdx.y * 32;
    #pragma unroll
    for (int j = threadIdx.y; j < 32; j += 8)
        t[j][threadIdx.x] = in[(size_t)(y0 + j) * D_ + x];
    __syncthreads();
    int x2 = blockIdx.y * 32 + threadIdx.x;
    int y2 = blockIdx.x * 32;
    #pragma unroll
    for (int j = threadIdx.y; j < 32; j += 8)
        out[(size_t)(y2 + j) * D_ + x2] = t[threadIdx.x][j];
}

// ---------------- LayerNorm + exact GELU, in place ----------------
__global__ __launch_bounds__(256) void ln_gelu_kernel(
    float* __restrict__ X, const float* __restrict__ g, const float* __restrict__ be)
{
    __shared__ float sh[256];
    int row = blockIdx.x;
    float* xr = X + (size_t)row * D_;
    float v[4]; float s = 0.f, s2 = 0.f;
    #pragma unroll
    for (int i = 0; i < 4; i++) {
        int c = threadIdx.x + i * 256;
        v[i] = xr[c]; s += v[i]; s2 += v[i] * v[i];
    }
    sh[threadIdx.x] = s; __syncthreads();
    for (int st = 128; st > 0; st >>= 1) {
        if (threadIdx.x < st) sh[threadIdx.x] += sh[threadIdx.x + st];
        __syncthreads();
    }
    float mean = sh[0] * (1.f / D_); __syncthreads();
    sh[threadIdx.x] = s2; __syncthreads();
    for (int st = 128; st > 0; st >>= 1) {
        if (threadIdx.x < st) sh[threadIdx.x] += sh[threadIdx.x + st];
        __syncthreads();
    }
    float var  = sh[0] * (1.f / D_) - mean * mean;
    float rstd = rsqrtf(var + 1e-5f);
    #pragma unroll
    for (int i = 0; i < 4; i++) {
        int c = threadIdx.x + i * 256;
        float y = (v[i] - mean) * rstd * g[c] + be[c];
        xr[c] = 0.5f * y * (1.f + erff(y * 0.7071067811865475f));
    }
}

// ---------------- per-row sum of squares + reciprocal norm ----------------
__global__ __launch_bounds__(256) void row_stats_kernel(
    const float* __restrict__ X, float* __restrict__ sq, float* __restrict__ rn)
{
    __shared__ float sh[256];
    int row = blockIdx.x;
    const float* xr = X + (size_t)row * D_;
    float s2 = 0.f;
    #pragma unroll
    for (int i = 0; i < 4; i++) { float v = xr[threadIdx.x + i * 256]; s2 += v * v; }
    sh[threadIdx.x] = s2; __syncthreads();
    for (int st = 128; st > 0; st >>= 1) {
        if (threadIdx.x < st) sh[threadIdx.x] += sh[threadIdx.x + st];
        __syncthreads();
    }
    if (threadIdx.x == 0) { sq[row] = sh[0]; rn[row] = rsqrtf(sh[0]); }
}

// ---------------- softmax stats per (b,h): two-pass (max, then sum-exp) --------
__global__ __launch_bounds__(256) void softmax_stats_kernel(
    const float* __restrict__ S, float* __restrict__ Mo, float* __restrict__ Lo)
{
    int b = blockIdx.x, h = blockIdx.y;
    int tid = threadIdx.x;
    const float4* row = (const float4*)(S + ((size_t)h * BQ_ + b) * NC_);
    __shared__ float sm[256], sl[256];

    float m = -1e30f;
    for (int i = tid; i < NC_ / 4; i += 256) {
        float4 v = row[i];
        m = fmaxf(m, fmaxf(fmaxf(v.x, v.y), fmaxf(v.z, v.w)));
    }
    sm[tid] = m; __syncthreads();
    for (int st = 128; st > 0; st >>= 1) {
        if (tid < st) sm[tid] = fmaxf(sm[tid], sm[tid + st]);
        __syncthreads();
    }
    m = sm[0];

    float l = 0.f;
    for (int i = tid; i < NC_ / 4; i += 256) {
        float4 v = row[i];
        l += __expf(v.x - m) + __expf(v.y - m) + __expf(v.z - m) + __expf(v.w - m);
    }
    sl[tid] = l; __syncthreads();
    for (int st = 128; st > 0; st >>= 1) {
        if (tid < st) sl[tid] += sl[tid + st];
        __syncthreads();
    }
    if (tid == 0) { Mo[b * H_ + h] = m; Lo[b * H_ + h] = sl[0]; }
}

// ---------------- final fused: features + fusion MLP + sigmoid ----------------
__global__ __launch_bounds__(256) void final_kernel(
    const float* __restrict__ GQK, const float* __restrict__ S,
    const float* __restrict__ qsq, const float* __restrict__ qrn,
    const float* __restrict__ ksq, const float* __restrict__ krn,
    const float* __restrict__ Mst, const float* __restrict__ Lst,
    const float* __restrict__ fw1, const float* __restrict__ fb1,
    const float* __restrict__ fw2, const float* __restrict__ fb2,
    const float* __restrict__ temp, float* __restrict__ out)
{
    __shared__ float sW1[192], sB1[64], sW2[64];
    __shared__ float sM[8], sIL[8];
    __shared__ float sb2, sET, sQsq, sQrn;
    int tid = threadIdx.x;
    int b = blockIdx.y;
    if (tid < 192) sW1[tid] = fw1[tid];
    if (tid < 64) { sB1[tid] = fb1[tid]; sW2[tid] = fw2[tid]; }
    if (tid < 8)  { sM[tid] = Mst[b * H_ + tid]; sIL[tid] = 1.f / Lst[b * H_ + tid]; }
    if (tid == 0) { sb2 = fb2[0]; sET = expf(temp[0]); sQsq = qsq[b]; sQrn = qrn[b]; }
    __syncthreads();

    int n = blockIdx.x * 256 + tid;
    float g = GQK[(size_t)b * NC_ + n];
    float cosv = g * sQrn * krn[n] * sET;
    float d2 = fmaxf(sQsq + ksq[n] - 2.f * g, 0.f);
    float euc = 1.f / (1.f + sqrtf(d2));
    float lsum = 0.f;
    #pragma unroll
    for (int h = 0; h < 8; h++) {
        float s = S[((size_t)h * BQ_ + b) * NC_ + n];
        lsum += __expf(s - sM[h]) * sIL[h];
    }
    float learned = 0.125f * lsum;

    float logit = sb2;
    #pragma unroll 16
    for (int j = 0; j < 64; j++) {
        float hv = cosv * sW1[j] + euc * sW1[64 + j] + learned * sW1[128 + j] + sB1[j];
        hv = fmaxf(hv, 0.f);
        logit += hv * sW2[j];
    }
    out[(size_t)b * NC_ + n] = 1.f / (1.f + __expf(-logit));
}

// ------------------------------- launcher -------------------------------------
extern "C" void kernel_launch(void* const* d_in, const int* in_sizes, int n_in,
                              void* d_out, int out_size)
{
    const float* qf   = (const float*)d_in[0];
    const float* cf   = (const float*)d_in[1];
    const float* temp = (const float*)d_in[2];
    const float* q_w1 = (const float*)d_in[3];
    const float* q_b1 = (const float*)d_in[4];
    const float* q_g  = (const float*)d_in[5];
    const float* q_be = (const float*)d_in[6];
    const float* q_w2 = (const float*)d_in[7];
    const float* q_b2 = (const float*)d_in[8];
    const float* k_w1 = (const float*)d_in[9];
    const float* k_b1 = (const float*)d_in[10];
    const float* k_g  = (const float*)d_in[11];
    const float* k_be = (const float*)d_in[12];
    const float* k_w2 = (const float*)d_in[13];
    const float* k_b2 = (const float*)d_in[14];
    const float* wq   = (const float*)d_in[15];
    const float* bq   = (const float*)d_in[16];
    const float* wk   = (const float*)d_in[17];
    const float* bk   = (const float*)d_in[18];
    const float* fw1  = (const float*)d_in[19];
    const float* fb1  = (const float*)d_in[20];
    const float* fw2  = (const float*)d_in[21];
    const float* fb2  = (const float*)d_in[22];

    float *buf, *KP, *KH, *qbuf, *QP, *QH, *GQK, *S, *Wt;
    float *ksq, *krn, *qsq, *qrn, *Mst, *Lst;
    cudaGetSymbolAddress((void**)&buf,  g_buf);
    cudaGetSymbolAddress((void**)&KP,   g_KP);
    cudaGetSymbolAddress((void**)&KH,   g_KH);
    cudaGetSymbolAddress((void**)&qbuf, g_qbuf);
    cudaGetSymbolAddress((void**)&QP,   g_QP);
    cudaGetSymbolAddress((void**)&QH,   g_QH);
    cudaGetSymbolAddress((void**)&GQK,  g_GQK);
    cudaGetSymbolAddress((void**)&S,    g_S);
    cudaGetSymbolAddress((void**)&Wt,   g_Wt);
    cudaGetSymbolAddress((void**)&ksq,  g_ksq);
    cudaGetSymbolAddress((void**)&krn,  g_krn);
    cudaGetSymbolAddress((void**)&qsq,  g_qsq);
    cudaGetSymbolAddress((void**)&qrn,  g_qrn);
    cudaGetSymbolAddress((void**)&Mst,  g_m);
    cudaGetSymbolAddress((void**)&Lst,  g_l);

    static const size_t WSZ = (size_t)D_ * D_;
    float* Wt_kw1 = Wt + 0 * WSZ;
    float* Wt_kw2 = Wt + 1 * WSZ;
    float* Wt_wk  = Wt + 2 * WSZ;
    float* Wt_qw1 = Wt + 3 * WSZ;
    float* Wt_qw2 = Wt + 4 * WSZ;
    float* Wt_wq  = Wt + 5 * WSZ;

    // ---- weight transposes (W[K,N] -> Wt[N,K]) ----
    dim3 tb(32, 8), tg(32, 32);
    transpose_k<<<tg, tb>>>(k_w1, Wt_kw1);
    transpose_k<<<tg, tb>>>(k_w2, Wt_kw2);
    transpose_k<<<tg, tb>>>(wk,   Wt_wk);
    transpose_k<<<tg, tb>>>(q_w1, Wt_qw1);
    transpose_k<<<tg, tb>>>(q_w2, Wt_qw2);
    transpose_k<<<tg, tb>>>(wq,   Wt_wq);

    // ---- key path ----
    mma_gemm_nt<<<dim3(D_/128, NC_/128, 1), 256>>>(
        cf, Wt_kw1, k_b1, buf, D_, D_, D_, D_, 0, (size_t)0, 1.f);
    ln_gelu_kernel<<<NC_, 256>>>(buf, k_g, k_be);
    mma_gemm_nt<<<dim3(D_/128, NC_/128, 1), 256>>>(
        buf, Wt_kw2, k_b2, KP, D_, D_, D_, D_, 0, (size_t)0, 1.f);
    mma_gemm_nt<<<dim3(D_/128, NC_/128, 1), 256>>>(
        KP, Wt_wk, bk, KH, D_, D_, D_, D_, 0, (size_t)0, 1.f);
    row_stats_kernel<<<NC_, 256>>>(KP, ksq, krn);

    // ---- query path ----
    mma_gemm_nt<<<dim3(D_/128, BQ_/128, 1), 256>>>(
        qf, Wt_qw1, q_b1, qbuf, D_, D_, D_, D_, 0, (size_t)0, 1.f);
    ln_gelu_kernel<<<BQ_, 256>>>(qbuf, q_g, q_be);
    mma_gemm_nt<<<dim3(D_/128, BQ_/128, 1), 256>>>(
        qbuf, Wt_qw2, q_b2, QP, D_, D_, D_, D_, 0, (size_t)0, 1.f);
    mma_gemm_nt<<<dim3(D_/128, BQ_/128, 1), 256>>>(
        QP, Wt_wq, bq, QH, D_, D_, D_, D_, 0, (size_t)0, 1.f);
    row_stats_kernel<<<BQ_, 256>>>(QP, qsq, qrn);

    // ---- pairwise ----
    mma_gemm_nt<<<dim3(NC_/128, BQ_/128, 1), 256>>>(
        QP, KP, (const float*)nullptr, GQK, D_, D_, D_, NC_, 0, (size_t)0, 1.f);
    mma_gemm_nt<<<dim3(NC_/128, BQ_/128, H_), 256>>>(
        QH, KH, (const float*)nullptr, S, HD_, D_, D_, NC_, HD_, (size_t)BQ_ * NC_,
        0.08838834764831845f /* 1/sqrt(128) */);

    softmax_stats_kernel<<<dim3(BQ_, H_), 256>>>(S, Mst, Lst);
    final_kernel<<<dim3(NC_/256, BQ_), 256>>>(
        GQK, S, qsq, qrn, ksq, krn, Mst, Lst, fw1, fb1, fw2, fb2, temp, (float*)d_out);
}